// round 8
// baseline (speedup 1.0000x reference)
#include <cuda_runtime.h>

#define D_MODEL   1024
#define NUM_HEADS 16
#define HEAD_DIM  64
#define BATCH     4
#define SEQ       2048
#define MTOT      (BATCH * SEQ)

// Scratch (allocation-free: __device__ globals). 4 x 32 MB.
__device__ float g_Q [MTOT * D_MODEL];
__device__ float g_K [MTOT * D_MODEL];
__device__ float g_V [MTOT * D_MODEL];
__device__ float g_AO[MTOT * D_MODEL];

// ---------------------------------------------------------------------------
// tf32 mma helpers (numerics validated R6/R7)
// ---------------------------------------------------------------------------
__device__ __forceinline__ unsigned f2tf32(float x) {
    unsigned u;
    asm("cvt.rna.tf32.f32 %0, %1;" : "=r"(u) : "f"(x));
    return u;
}

__device__ __forceinline__ void mma_tf32(float c[4], const unsigned a[4],
                                         const unsigned b[2]) {
    asm volatile(
        "mma.sync.aligned.m16n8k8.row.col.f32.tf32.tf32.f32 "
        "{%0,%1,%2,%3}, {%4,%5,%6,%7}, {%8,%9}, {%0,%1,%2,%3};"
        : "+f"(c[0]), "+f"(c[1]), "+f"(c[2]), "+f"(c[3])
        : "r"(a[0]), "r"(a[1]), "r"(a[2]), "r"(a[3]), "r"(b[0]), "r"(b[1]));
}

// XOR swizzle for fragment blocks. Applied to the intra-block word offset;
// value is a multiple of 4 -> preserves uint2/uint4 alignment. Constant per
// fragment-load instruction -> reads stay conflict-free; varies with the
// block coordinates -> staging writes spread across banks.
__device__ __forceinline__ int swz(int u, int v) {
    return (((u ^ v) & 3) << 3) | ((((u >> 2) ^ (v >> 2)) & 1) << 2);
}

// ---------------------------------------------------------------------------
// tf32 GEMM (NT), fragment-packed smem.
// C[M,N] = A[M,K] @ W[N,K]^T + bias[N].
// Block 128x128, BK=32, 8 warps (2m x 4n), warp 64x32 = 4x4 m16n8k8.
//
// A-fragment storage (per 32-k tile): value A[r][c] (r<128, c<32) lives at
//   word  ((r>>4)*4 + (c>>3))*128  +  [ ((r&7)*16 + (c&3)*4 + ((r>>3)&1) + 2*((c>>2)&1)) ^ swz(c>>3, r>>4) ]
// so the 4 regs of an A-fragment are one uint4 at lane*4.
// W-fragment storage: value W[n][c] at
//   word  ((n>>3)*4 + (c>>3))*64   +  [ ((n&7)*8 + (c&3)*2 + ((c>>2)&1)) ^ swz(c>>3, n>>3) ]
// so the 2 regs of a B-fragment are one uint2 at lane*2.
// ---------------------------------------------------------------------------
template <bool SCATTER>
__global__ __launch_bounds__(256)
void gemm_tf32_kernel(const float* __restrict__ A, const float* __restrict__ W,
                      const float* __restrict__ bias, float* __restrict__ C)
{
    const int K = D_MODEL;
    __shared__ __align__(16) unsigned As[4096];   // 16 KB
    __shared__ __align__(16) unsigned Ws[4096];   // 16 KB

    const int tid    = threadIdx.x;
    const int wid    = tid >> 5;
    const int lane   = tid & 31;
    const int warp_m = wid >> 2;
    const int warp_n = wid & 3;
    const int m0     = blockIdx.y * 128;
    const int n0     = blockIdx.x * 128;

    const int grow = tid >> 1;            // 0..127
    const int gcol = (tid & 1) * 16;      // 0 or 16
    const float* aptr = A + (size_t)(m0 + grow) * K + gcol;
    const float* wptr = W + (size_t)(n0 + grow) * K + gcol;

    // staging write invariants
    const int a_rbase = (grow >> 4) * 4;            // A block row part
    const int a_roff  = (grow & 7) * 16 + ((grow >> 3) & 1);
    const int a_rsw   = grow >> 4;
    const int w_rbase = (grow >> 3) * 4;            // W block row part
    const int w_roff  = (grow & 7) * 8;
    const int w_rsw   = grow >> 3;

    float acc[4][4][4];
#pragma unroll
    for (int i = 0; i < 4; i++)
#pragma unroll
        for (int j = 0; j < 4; j++)
#pragma unroll
            for (int r = 0; r < 4; r++) acc[i][j][r] = 0.f;

    float4 avr[4], wvr[4];
#pragma unroll
    for (int i = 0; i < 4; i++) {
        avr[i] = *(const float4*)(aptr + i * 4);
        wvr[i] = *(const float4*)(wptr + i * 4);
    }

    for (int k0 = 0; k0 < K; k0 += 32) {
        __syncthreads();
#pragma unroll
        for (int i = 0; i < 4; i++) {
            const int c4 = gcol + i * 4;          // 4-aligned k col
            const int kb = c4 >> 3;
            const int sc = (c4 >> 2) & 1;
            // A writes
            {
                const int sw   = swz(kb, a_rsw);
                const int base = (a_rbase + kb) * 128 + a_roff + 2 * sc;
                As[(base +  0) ^ sw] = f2tf32(avr[i].x);
                As[(base +  4) ^ sw] = f2tf32(avr[i].y);
                As[(base +  8) ^ sw] = f2tf32(avr[i].z);
                As[(base + 12) ^ sw] = f2tf32(avr[i].w);
            }
            // W writes
            {
                const int sw   = swz(kb, w_rsw);
                const int base = (w_rbase + kb) * 64 + w_roff + sc;
                Ws[(base + 0) ^ sw] = f2tf32(wvr[i].x);
                Ws[(base + 2) ^ sw] = f2tf32(wvr[i].y);
                Ws[(base + 4) ^ sw] = f2tf32(wvr[i].z);
                Ws[(base + 6) ^ sw] = f2tf32(wvr[i].w);
            }
        }
        __syncthreads();

        if (k0 + 32 < K) {
#pragma unroll
            for (int i = 0; i < 4; i++) {
                avr[i] = *(const float4*)(aptr + k0 + 32 + i * 4);
                wvr[i] = *(const float4*)(wptr + k0 + 32 + i * 4);
            }
        }

#pragma unroll
        for (int k8 = 0; k8 < 4; k8++) {
            unsigned af[4][4];
            uint2    bf[4];
#pragma unroll
            for (int mt = 0; mt < 4; mt++) {
                const int mg = warp_m * 4 + mt;
                *(uint4*)af[mt] = *(const uint4*)
                    &As[(((mg * 4 + k8) * 128) + lane * 4) ^ swz(k8, mg)];
            }
#pragma unroll
            for (int nt = 0; nt < 4; nt++) {
                const int ng = warp_n * 4 + nt;
                bf[nt] = *(const uint2*)
                    &Ws[(((ng * 4 + k8) * 64) + lane * 2) ^ swz(k8, ng)];
            }
#pragma unroll
            for (int mt = 0; mt < 4; mt++)
#pragma unroll
                for (int nt = 0; nt < 4; nt++)
                    mma_tf32(acc[mt][nt], af[mt], (const unsigned*)&bf[nt]);
        }
    }

    // Epilogue (fragment layout identical to R6/R7)
    const int gid = lane >> 2;
    const int tig = lane & 3;
#pragma unroll
    for (int nt = 0; nt < 4; nt++) {
        const int n  = n0 + warp_n * 32 + nt * 8 + tig * 2;
        const float b0 = bias[n], b1 = bias[n + 1];
#pragma unroll
        for (int mt = 0; mt < 4; mt++) {
            const int m = m0 + warp_m * 64 + mt * 16 + gid;
            float2 v0 = make_float2(acc[mt][nt][0] + b0, acc[mt][nt][1] + b1);
            float2 v1 = make_float2(acc[mt][nt][2] + b0, acc[mt][nt][3] + b1);
            if (SCATTER) {
                const int h  = n >> 6;
                const int hd = n & 63;
                const int bb = m >> 11;
                const int s  = m & (SEQ - 1);
                float* p0 = C + ((size_t)((bb * NUM_HEADS + h) * SEQ + s))     * HEAD_DIM + hd;
                float* p1 = C + ((size_t)((bb * NUM_HEADS + h) * SEQ + s + 8)) * HEAD_DIM + hd;
                *(float2*)p0 = v0;
                *(float2*)p1 = v1;
            } else {
                *(float2*)(C + (size_t)m * D_MODEL + n)       = v0;
                *(float2*)(C + (size_t)(m + 8) * D_MODEL + n) = v1;
            }
        }
    }
}

// ---------------------------------------------------------------------------
// Flash attention v4: tf32 tensor cores, fragment-packed K/V smem,
// Q A-fragments in registers, half-width P buffer with two-pass PV.
// Br = Bc = 128, Hd = 64, 8 warps; warp w owns S rows [16w, 16w+16).
//
// K fragment storage (tile 128 kv x 64 hd; QK^T B-operand):
//   value K[n][c] -> word (n>>3)*8*64 + (c>>3)*64 +
//                    [ ((n&7)*8 + (c&3)*2 + ((c>>2)&1)) ^ swz(c>>3, n>>3) ]
// V fragment storage (tile 128 kv x 64 hd; PV B-operand, kv is the k-dim):
//   value V[r][c] -> word ((c>>3)*16 + (r>>3))*64 +
//                    [ ((c&7)*8 + (r&3)*2 + ((r>>2)&1)) ^ swz(r>>3, c>>3) ]
// Both give the 2-reg B-fragment as one uint2 at lane*2 (conflict-free).
// P: strided [128][68] fp->tf32, 64 kv columns per pass.
// ---------------------------------------------------------------------------
#define FPS2 68
#define FA_SMEM ((8192 + 8192 + 128 * FPS2) * 4)   // 100,352 B

__global__ __launch_bounds__(256, 1)
void flash_attn_tc_kernel(const float* __restrict__ Q, const float* __restrict__ K,
                          const float* __restrict__ V, float* __restrict__ AO)
{
    extern __shared__ __align__(16) unsigned smu[];
    unsigned* KF = smu;              // 8192 words
    unsigned* VF = KF + 8192;        // 8192 words
    unsigned* Ps = VF + 8192;        // 128*68 words

    const int tid  = threadIdx.x;
    const int w    = tid >> 5;
    const int lane = tid & 31;
    const int gid  = lane >> 2;
    const int tig  = lane & 3;
    const int bh   = blockIdx.y;
    const int q0   = blockIdx.x * 128;
    const float scale = 0.125f;      // HEAD_DIM^-0.5

    const float* Qb = Q + (size_t)bh * SEQ * HEAD_DIM;
    const float* Kb = K + (size_t)bh * SEQ * HEAD_DIM;
    const float* Vb = V + (size_t)bh * SEQ * HEAD_DIM;

    // ---- Q A-fragments in registers (each warp reads only its 16 rows) ----
    unsigned qf[8][4];
    {
        const float* q0p = Qb + (size_t)(q0 + w * 16 + gid) * HEAD_DIM;
        const float* q1p = q0p + 8 * HEAD_DIM;
#pragma unroll
        for (int m = 0; m < 8; m++) {
            qf[m][0] = f2tf32(q0p[m * 8 + tig]     * scale);
            qf[m][1] = f2tf32(q1p[m * 8 + tig]     * scale);
            qf[m][2] = f2tf32(q0p[m * 8 + tig + 4] * scale);
            qf[m][3] = f2tf32(q1p[m * 8 + tig + 4] * scale);
        }
    }

    const int r0l = w * 16 + gid;    // local S row (upper)

    float m0v = -1e30f, m1v = -1e30f, l0 = 0.f, l1 = 0.f;
    float oacc[8][4];
#pragma unroll
    for (int nt = 0; nt < 8; nt++)
#pragma unroll
        for (int r = 0; r < 4; r++) oacc[nt][r] = 0.f;

    for (int kv0 = 0; kv0 < SEQ; kv0 += 128) {
        __syncthreads();   // all warps done reading KF/VF of previous tile
#pragma unroll
        for (int it = 0; it < 8; it++) {
            const int idx = tid + it * 256;
            const int r   = idx >> 4;            // kv row 0..127
            const int c4  = (idx & 15) * 4;      // hd col, 4-aligned
            const float4 kv4 = *(const float4*)(Kb + (size_t)(kv0 + r) * HEAD_DIM + c4);
            const float4 vv4 = *(const float4*)(Vb + (size_t)(kv0 + r) * HEAD_DIM + c4);
            // K packed write
            {
                const int sw   = swz(c4 >> 3, r >> 3);
                const int base = ((r >> 3) * 8 + (c4 >> 3)) * 64
                               + (r & 7) * 8 + ((c4 >> 2) & 1);
                KF[(base + 0) ^ sw] = f2tf32(kv4.x);
                KF[(base + 2) ^ sw] = f2tf32(kv4.y);
                KF[(base + 4) ^ sw] = f2tf32(kv4.z);
                KF[(base + 6) ^ sw] = f2tf32(kv4.w);
            }
            // V packed write
            {
                const int sw   = swz(r >> 3, c4 >> 3);
                const int base = ((c4 >> 3) * 16 + (r >> 3)) * 64
                               + (r & 3) * 2 + ((r >> 2) & 1);
                const int g0   = (c4 & 7);       // 0 or 4
                VF[(base + (g0 + 0) * 8) ^ sw] = f2tf32(vv4.x);
                VF[(base + (g0 + 1) * 8) ^ sw] = f2tf32(vv4.y);
                VF[(base + (g0 + 2) * 8) ^ sw] = f2tf32(vv4.z);
                VF[(base + (g0 + 3) * 8) ^ sw] = f2tf32(vv4.w);
            }
        }
        __syncthreads();

        // ---- S = Q K^T : warp computes 16 rows x 128 cols ----
        float sacc[16][4];
#pragma unroll
        for (int nt = 0; nt < 16; nt++)
#pragma unroll
            for (int r = 0; r < 4; r++) sacc[nt][r] = 0.f;

#pragma unroll
        for (int kkb = 0; kkb < 8; kkb++) {
#pragma unroll
            for (int nt = 0; nt < 16; nt++) {
                const uint2 b = *(const uint2*)
                    &KF[(((nt * 8 + kkb) * 64) + lane * 2) ^ swz(kkb, nt)];
                mma_tf32(sacc[nt], qf[kkb], (const unsigned*)&b);
            }
        }

        // ---- online softmax (rows r0l via c0/c1, r0l+8 via c2/c3) ----
        float rm0 = -1e30f, rm1 = -1e30f;
#pragma unroll
        for (int nt = 0; nt < 16; nt++) {
            rm0 = fmaxf(rm0, fmaxf(sacc[nt][0], sacc[nt][1]));
            rm1 = fmaxf(rm1, fmaxf(sacc[nt][2], sacc[nt][3]));
        }
        rm0 = fmaxf(rm0, __shfl_xor_sync(0xffffffffu, rm0, 1));
        rm0 = fmaxf(rm0, __shfl_xor_sync(0xffffffffu, rm0, 2));
        rm1 = fmaxf(rm1, __shfl_xor_sync(0xffffffffu, rm1, 1));
        rm1 = fmaxf(rm1, __shfl_xor_sync(0xffffffffu, rm1, 2));

        const float mn0 = fmaxf(m0v, rm0);
        const float mn1 = fmaxf(m1v, rm1);
        const float al0 = __expf(m0v - mn0);
        const float al1 = __expf(m1v - mn1);
        m0v = mn0; m1v = mn1;

        float rs0 = 0.f, rs1 = 0.f;
#pragma unroll
        for (int nt = 0; nt < 16; nt++) {
            sacc[nt][0] = __expf(sacc[nt][0] - mn0);
            sacc[nt][1] = __expf(sacc[nt][1] - mn0);
            sacc[nt][2] = __expf(sacc[nt][2] - mn1);
            sacc[nt][3] = __expf(sacc[nt][3] - mn1);
            rs0 += sacc[nt][0] + sacc[nt][1];
            rs1 += sacc[nt][2] + sacc[nt][3];
        }
        rs0 += __shfl_xor_sync(0xffffffffu, rs0, 1);
        rs0 += __shfl_xor_sync(0xffffffffu, rs0, 2);
        rs1 += __shfl_xor_sync(0xffffffffu, rs1, 1);
        rs1 += __shfl_xor_sync(0xffffffffu, rs1, 2);
        l0 = l0 * al0 + rs0;
        l1 = l1 * al1 + rs1;

#pragma unroll
        for (int nt = 0; nt < 8; nt++) {
            oacc[nt][0] *= al0; oacc[nt][1] *= al0;
            oacc[nt][2] *= al1; oacc[nt][3] *= al1;
        }

        // ---- O += P V, two passes of 64 kv columns (P rows warp-private) --
#pragma unroll
        for (int pass = 0; pass < 2; pass++) {
            __syncwarp();          // previous pass's P reads complete
#pragma unroll
            for (int ntl = 0; ntl < 8; ntl++) {
                const int nts = pass * 8 + ntl;
                uint2 u01 = make_uint2(f2tf32(sacc[nts][0]), f2tf32(sacc[nts][1]));
                uint2 u23 = make_uint2(f2tf32(sacc[nts][2]), f2tf32(sacc[nts][3]));
                *(uint2*)&Ps[(r0l)     * FPS2 + ntl * 8 + 2 * tig] = u01;
                *(uint2*)&Ps[(r0l + 8) * FPS2 + ntl * 8 + 2 * tig] = u23;
            }
            __syncwarp();
#pragma unroll
            for (int j = 0; j < 8; j++) {
                const int kkb = pass * 8 + j;
                unsigned ap[4];
                ap[0] = Ps[(r0l)     * FPS2 + j * 8 + tig];
                ap[1] = Ps[(r0l + 8) * FPS2 + j * 8 + tig];
                ap[2] = Ps[(r0l)     * FPS2 + j * 8 + tig + 4];
                ap[3] = Ps[(r0l + 8) * FPS2 + j * 8 + tig + 4];
#pragma unroll
                for (int nt = 0; nt < 8; nt++) {
                    const uint2 b = *(const uint2*)
                        &VF[(((nt * 16 + kkb) * 64) + lane * 2) ^ swz(kkb, nt)];
                    mma_tf32(oacc[nt], ap, (const unsigned*)&b);
                }
            }
        }
    }

    // Epilogue: normalize, write [B,S,D]
    const int b = bh >> 4;
    const int h = bh & 15;
    const float inv0 = 1.0f / l0;
    const float inv1 = 1.0f / l1;
#pragma unroll
    for (int nt = 0; nt < 8; nt++) {
        const int col = h * HEAD_DIM + nt * 8 + 2 * tig;
        float2 v0 = make_float2(oacc[nt][0] * inv0, oacc[nt][1] * inv0);
        float2 v1 = make_float2(oacc[nt][2] * inv1, oacc[nt][3] * inv1);
        *(float2*)(AO + (size_t)(b * SEQ + q0 + r0l)     * D_MODEL + col) = v0;
        *(float2*)(AO + (size_t)(b * SEQ + q0 + r0l + 8) * D_MODEL + col) = v1;
    }
}

// ---------------------------------------------------------------------------
extern "C" void kernel_launch(void* const* d_in, const int* in_sizes, int n_in,
                              void* d_out, int out_size)
{
    const float* x  = (const float*)d_in[0];
    const float* wq = (const float*)d_in[1];
    const float* bq = (const float*)d_in[2];
    const float* wk = (const float*)d_in[3];
    const float* bk = (const float*)d_in[4];
    const float* wv = (const float*)d_in[5];
    const float* bv = (const float*)d_in[6];
    const float* wo = (const float*)d_in[7];
    const float* bo = (const float*)d_in[8];

    float *Qp, *Kp, *Vp, *AOp;
    cudaGetSymbolAddress((void**)&Qp,  g_Q);
    cudaGetSymbolAddress((void**)&Kp,  g_K);
    cudaGetSymbolAddress((void**)&Vp,  g_V);
    cudaGetSymbolAddress((void**)&AOp, g_AO);

    const dim3 pg(D_MODEL / 128, MTOT / 128);   // (8, 64)

    gemm_tf32_kernel<true><<<pg, 256>>>(x, wq, bq, Qp);
    gemm_tf32_kernel<true><<<pg, 256>>>(x, wk, bk, Kp);
    gemm_tf32_kernel<true><<<pg, 256>>>(x, wv, bv, Vp);

    cudaFuncSetAttribute(flash_attn_tc_kernel,
                         cudaFuncAttributeMaxDynamicSharedMemorySize, FA_SMEM);
    flash_attn_tc_kernel<<<dim3(SEQ / 128, BATCH * NUM_HEADS), 256, FA_SMEM>>>(Qp, Kp, Vp, AOp);

    gemm_tf32_kernel<false><<<pg, 256>>>(AOp, wo, bo, (float*)d_out);
}

// round 10
// speedup vs baseline: 1.4591x; 1.4591x over previous
#include <cuda_runtime.h>
#include <cuda_fp16.h>

#define D_MODEL   1024
#define NUM_HEADS 16
#define HEAD_DIM  64
#define BATCH     4
#define SEQ       2048
#define MTOT      (BATCH * SEQ)

// Scratch (allocation-free: __device__ globals). 4 x 32 MB.
__device__ float g_Q [MTOT * D_MODEL];
__device__ float g_K [MTOT * D_MODEL];
__device__ float g_V [MTOT * D_MODEL];
__device__ float g_AO[MTOT * D_MODEL];

// ---------------------------------------------------------------------------
// mma helpers
// ---------------------------------------------------------------------------
__device__ __forceinline__ unsigned f2tf32(float x) {
    unsigned u;
    asm("cvt.rna.tf32.f32 %0, %1;" : "=r"(u) : "f"(x));
    return u;
}

__device__ __forceinline__ void mma_tf32(float c[4], const unsigned a[4],
                                         const unsigned b[2]) {
    asm volatile(
        "mma.sync.aligned.m16n8k8.row.col.f32.tf32.tf32.f32 "
        "{%0,%1,%2,%3}, {%4,%5,%6,%7}, {%8,%9}, {%0,%1,%2,%3};"
        : "+f"(c[0]), "+f"(c[1]), "+f"(c[2]), "+f"(c[3])
        : "r"(a[0]), "r"(a[1]), "r"(a[2]), "r"(a[3]), "r"(b[0]), "r"(b[1]));
}

__device__ __forceinline__ void mma_f16(float c[4], const unsigned a[4],
                                        const unsigned b[2]) {
    asm volatile(
        "mma.sync.aligned.m16n8k16.row.col.f32.f16.f16.f32 "
        "{%0,%1,%2,%3}, {%4,%5,%6,%7}, {%8,%9}, {%0,%1,%2,%3};"
        : "+f"(c[0]), "+f"(c[1]), "+f"(c[2]), "+f"(c[3])
        : "r"(a[0]), "r"(a[1]), "r"(a[2]), "r"(a[3]), "r"(b[0]), "r"(b[1]));
}

__device__ __forceinline__ unsigned h2u(__half2 h) {
    return *reinterpret_cast<unsigned*>(&h);
}

// ---------------------------------------------------------------------------
// tf32 tensor-core GEMM (NT) — EXACT R7 version (measured ~171 us each).
// C[M,N] = A[M,K] @ W[N,K]^T + bias[N]
// ---------------------------------------------------------------------------
#define GS 36   // smem row stride (words) for 32 k-columns

template <bool SCATTER>
__global__ __launch_bounds__(256)
void gemm_tf32_kernel(const float* __restrict__ A, const float* __restrict__ W,
                      const float* __restrict__ bias, float* __restrict__ C)
{
    const int K = D_MODEL;
    __shared__ unsigned As[128 * GS];
    __shared__ unsigned Ws[128 * GS];

    const int tid    = threadIdx.x;
    const int wid    = tid >> 5;
    const int lane   = tid & 31;
    const int gid    = lane >> 2;
    const int tig    = lane & 3;
    const int warp_m = wid >> 2;
    const int warp_n = wid & 3;
    const int m0     = blockIdx.y * 128;
    const int n0     = blockIdx.x * 128;

    const int grow = tid >> 1;
    const int gcol = (tid & 1) * 16;
    const float* aptr = A + (size_t)(m0 + grow) * K + gcol;
    const float* wptr = W + (size_t)(n0 + grow) * K + gcol;

    float acc[4][4][4];
#pragma unroll
    for (int i = 0; i < 4; i++)
#pragma unroll
        for (int j = 0; j < 4; j++)
#pragma unroll
            for (int r = 0; r < 4; r++) acc[i][j][r] = 0.f;

    float4 avr[4], wvr[4];
#pragma unroll
    for (int i = 0; i < 4; i++) {
        avr[i] = *(const float4*)(aptr + i * 4);
        wvr[i] = *(const float4*)(wptr + i * 4);
    }

    for (int k0 = 0; k0 < K; k0 += 32) {
        __syncthreads();
#pragma unroll
        for (int i = 0; i < 4; i++) {
            const int c = gcol + i * 4;
            As[grow * GS + c + 0] = f2tf32(avr[i].x);
            As[grow * GS + c + 1] = f2tf32(avr[i].y);
            As[grow * GS + c + 2] = f2tf32(avr[i].z);
            As[grow * GS + c + 3] = f2tf32(avr[i].w);
            Ws[grow * GS + c + 0] = f2tf32(wvr[i].x);
            Ws[grow * GS + c + 1] = f2tf32(wvr[i].y);
            Ws[grow * GS + c + 2] = f2tf32(wvr[i].z);
            Ws[grow * GS + c + 3] = f2tf32(wvr[i].w);
        }
        __syncthreads();

        if (k0 + 32 < K) {
#pragma unroll
            for (int i = 0; i < 4; i++) {
                avr[i] = *(const float4*)(aptr + k0 + 32 + i * 4);
                wvr[i] = *(const float4*)(wptr + k0 + 32 + i * 4);
            }
        }

#pragma unroll
        for (int k8 = 0; k8 < 4; k8++) {
            const int kk = k8 * 8;
            unsigned a[4][4], b[4][2];
#pragma unroll
            for (int mt = 0; mt < 4; mt++) {
                const int m = warp_m * 64 + mt * 16 + gid;
                a[mt][0] = As[(m)     * GS + kk + tig];
                a[mt][1] = As[(m + 8) * GS + kk + tig];
                a[mt][2] = As[(m)     * GS + kk + tig + 4];
                a[mt][3] = As[(m + 8) * GS + kk + tig + 4];
            }
#pragma unroll
            for (int nt = 0; nt < 4; nt++) {
                const int n = warp_n * 32 + nt * 8 + gid;
                b[nt][0] = Ws[n * GS + kk + tig];
                b[nt][1] = Ws[n * GS + kk + tig + 4];
            }
#pragma unroll
            for (int mt = 0; mt < 4; mt++)
#pragma unroll
                for (int nt = 0; nt < 4; nt++)
                    mma_tf32(acc[mt][nt], a[mt], b[nt]);
        }
    }

#pragma unroll
    for (int nt = 0; nt < 4; nt++) {
        const int n  = n0 + warp_n * 32 + nt * 8 + tig * 2;
        const float b0 = bias[n], b1 = bias[n + 1];
#pragma unroll
        for (int mt = 0; mt < 4; mt++) {
            const int m = m0 + warp_m * 64 + mt * 16 + gid;
            float2 v0 = make_float2(acc[mt][nt][0] + b0, acc[mt][nt][1] + b1);
            float2 v1 = make_float2(acc[mt][nt][2] + b0, acc[mt][nt][3] + b1);
            if (SCATTER) {
                const int h  = n >> 6;
                const int hd = n & 63;
                const int bb = m >> 11;
                const int s  = m & (SEQ - 1);
                float* p0 = C + ((size_t)((bb * NUM_HEADS + h) * SEQ + s))     * HEAD_DIM + hd;
                float* p1 = C + ((size_t)((bb * NUM_HEADS + h) * SEQ + s + 8)) * HEAD_DIM + hd;
                *(float2*)p0 = v0;
                *(float2*)p1 = v1;
            } else {
                *(float2*)(C + (size_t)m * D_MODEL + n)       = v0;
                *(float2*)(C + (size_t)(m + 8) * D_MODEL + n) = v1;
            }
        }
    }
}

// ---------------------------------------------------------------------------
// Flash attention v6: fp16 m16n8k16, fp32 softmax, REGISTER-RESIDENT P.
// Br = Bc = 128, Hd = 64, 8 warps; warp w owns S rows [16w, 16w+16).
//
// Key identity: the QK^T C-fragment (thread (gid,tig) holds cols nt*8+2tig,
// +1 of rows r0l/r0l+8) is exactly the PV A-fragment for k-block kkb when
// nt = 2*kkb (k=16kkb+2tig,+1) and nt = 2*kkb+1 (k=16kkb+8+2tig,+1).
// So P = exp(S) stays in registers: no smem staging at all.
//
// K packed (QK^T B-operand): word kkb*1024 + n*8 + t*2 + j  holds
//   half2{ K[n][16kkb+2t+8j], K[n][16kkb+2t+8j+1] }
// V packed (PV B-operand):   word kkb*512 + n*8 + t*2 + j   holds
//   half2{ V[16kkb+2t+8j][n], V[16kkb+2t+8j+1][n] }
// B-fragment load = one uint2 at ...+(n-tile)*64 + lane-derived offset;
// each 16-lane phase of the LDS.64 covers all 32 banks once (conflict-free).
// ---------------------------------------------------------------------------
#define FA_SMEM ((4096 + 4096) * 4)   // 32,768 B

__global__ __launch_bounds__(256, 1)
void flash_attn_f16_kernel(const float* __restrict__ Q, const float* __restrict__ K,
                           const float* __restrict__ V, float* __restrict__ AO)
{
    extern __shared__ __align__(16) unsigned smu[];
    unsigned* KB = smu;              // 4096 words: [4][128][8]
    unsigned* VB = KB + 4096;        // 4096 words: [8][64][8]
    __half*   VH = reinterpret_cast<__half*>(VB);

    const int tid  = threadIdx.x;
    const int w    = tid >> 5;
    const int lane = tid & 31;
    const int gid  = lane >> 2;
    const int tig  = lane & 3;
    const int bh   = blockIdx.y;
    const int q0   = blockIdx.x * 128;
    const float scale = 0.125f;      // HEAD_DIM^-0.5

    const float* Qb = Q + (size_t)bh * SEQ * HEAD_DIM;
    const float* Kb = K + (size_t)bh * SEQ * HEAD_DIM;
    const float* Vb = V + (size_t)bh * SEQ * HEAD_DIM;

    // ---- Q A-fragments in registers (fp16), pre-scaled ----
    unsigned qf[4][4];
    {
        const float* q0p = Qb + (size_t)(q0 + w * 16 + gid) * HEAD_DIM;
        const float* q1p = q0p + 8 * HEAD_DIM;
#pragma unroll
        for (int kkb = 0; kkb < 4; kkb++) {
            const int c = kkb * 16 + 2 * tig;
            float2 x0 = *(const float2*)(q0p + c);
            float2 x1 = *(const float2*)(q1p + c);
            float2 x2 = *(const float2*)(q0p + c + 8);
            float2 x3 = *(const float2*)(q1p + c + 8);
            qf[kkb][0] = h2u(__floats2half2_rn(x0.x * scale, x0.y * scale));
            qf[kkb][1] = h2u(__floats2half2_rn(x1.x * scale, x1.y * scale));
            qf[kkb][2] = h2u(__floats2half2_rn(x2.x * scale, x2.y * scale));
            qf[kkb][3] = h2u(__floats2half2_rn(x3.x * scale, x3.y * scale));
        }
    }

    float m0v = -1e30f, m1v = -1e30f, l0 = 0.f, l1 = 0.f;
    float oacc[8][4];
#pragma unroll
    for (int nt = 0; nt < 8; nt++)
#pragma unroll
        for (int r = 0; r < 4; r++) oacc[nt][r] = 0.f;

    for (int kv0 = 0; kv0 < SEQ; kv0 += 128) {
        __syncthreads();   // all warps done reading KB/VB of previous tile
#pragma unroll
        for (int it = 0; it < 8; it++) {
            const int idx = tid + it * 256;
            const int r   = idx >> 4;            // kv row 0..127
            const int c4  = (idx & 15) * 4;      // hd col, 4-aligned
            const float4 kv4 = *(const float4*)(Kb + (size_t)(kv0 + r) * HEAD_DIM + c4);
            const float4 vv4 = *(const float4*)(Vb + (size_t)(kv0 + r) * HEAD_DIM + c4);
            // K packed write: half2 pairs p0 = c4/2 (x,y) and p0+1 (z,w).
            // word(p,r) = (p>>3)*1024 + r*8 + (p&3)*2 + ((p>>2)&1)
            {
                const int p0 = c4 >> 1;
                const int w0 = (p0 >> 3) * 1024 + r * 8 + (p0 & 3) * 2 + ((p0 >> 2) & 1);
                const int p1 = p0 + 1;
                const int w1 = (p1 >> 3) * 1024 + r * 8 + (p1 & 3) * 2 + ((p1 >> 2) & 1);
                KB[w0] = h2u(__floats2half2_rn(kv4.x, kv4.y));
                KB[w1] = h2u(__floats2half2_rn(kv4.z, kv4.w));
            }
            // V packed write: 4 scalar halves (vertical kv pairing)
            {
                const int word = (r >> 4) * 512 + c4 * 8
                               + ((r >> 1) & 3) * 2 + ((r >> 3) & 1);
                const int hoff = (r & 1);
                VH[(word +  0) * 2 + hoff] = __float2half_rn(vv4.x);
                VH[(word +  8) * 2 + hoff] = __float2half_rn(vv4.y);
                VH[(word + 16) * 2 + hoff] = __float2half_rn(vv4.z);
                VH[(word + 24) * 2 + hoff] = __float2half_rn(vv4.w);
            }
        }
        __syncthreads();

        // ---- S = Q K^T : 4 k-blocks x 16 n-tiles of m16n8k16 ----
        float sacc[16][4];
#pragma unroll
        for (int nt = 0; nt < 16; nt++)
#pragma unroll
            for (int r = 0; r < 4; r++) sacc[nt][r] = 0.f;

#pragma unroll
        for (int kkb = 0; kkb < 4; kkb++) {
#pragma unroll
            for (int nt = 0; nt < 16; nt++) {
                const uint2 b = *(const uint2*)
                    &KB[kkb * 1024 + (nt * 8 + gid) * 8 + tig * 2];
                mma_f16(sacc[nt], qf[kkb], (const unsigned*)&b);
            }
        }

        // ---- online softmax (fp32), exp'd values stay in sacc ----
        float rm0 = -1e30f, rm1 = -1e30f;
#pragma unroll
        for (int nt = 0; nt < 16; nt++) {
            rm0 = fmaxf(rm0, fmaxf(sacc[nt][0], sacc[nt][1]));
            rm1 = fmaxf(rm1, fmaxf(sacc[nt][2], sacc[nt][3]));
        }
        rm0 = fmaxf(rm0, __shfl_xor_sync(0xffffffffu, rm0, 1));
        rm0 = fmaxf(rm0, __shfl_xor_sync(0xffffffffu, rm0, 2));
        rm1 = fmaxf(rm1, __shfl_xor_sync(0xffffffffu, rm1, 1));
        rm1 = fmaxf(rm1, __shfl_xor_sync(0xffffffffu, rm1, 2));

        const float mn0 = fmaxf(m0v, rm0);
        const float mn1 = fmaxf(m1v, rm1);
        const float al0 = __expf(m0v - mn0);
        const float al1 = __expf(m1v - mn1);
        m0v = mn0; m1v = mn1;

        float rs0 = 0.f, rs1 = 0.f;
#pragma unroll
        for (int nt = 0; nt < 16; nt++) {
            sacc[nt][0] = __expf(sacc[nt][0] - mn0);
            sacc[nt][1] = __expf(sacc[nt][1] - mn0);
            sacc[nt][2] = __expf(sacc[nt][2] - mn1);
            sacc[nt][3] = __expf(sacc[nt][3] - mn1);
            rs0 += sacc[nt][0] + sacc[nt][1];
            rs1 += sacc[nt][2] + sacc[nt][3];
        }
        rs0 += __shfl_xor_sync(0xffffffffu, rs0, 1);
        rs0 += __shfl_xor_sync(0xffffffffu, rs0, 2);
        rs1 += __shfl_xor_sync(0xffffffffu, rs1, 1);
        rs1 += __shfl_xor_sync(0xffffffffu, rs1, 2);
        l0 = l0 * al0 + rs0;
        l1 = l1 * al1 + rs1;

#pragma unroll
        for (int nt = 0; nt < 8; nt++) {
            oacc[nt][0] *= al0; oacc[nt][1] *= al0;
            oacc[nt][2] *= al1; oacc[nt][3] *= al1;
        }

        // ---- O += P V : P directly from registers (C->A fragment identity)
#pragma unroll
        for (int kkb = 0; kkb < 8; kkb++) {
            unsigned ap[4];
            ap[0] = h2u(__floats2half2_rn(sacc[2*kkb][0],     sacc[2*kkb][1]));
            ap[1] = h2u(__floats2half2_rn(sacc[2*kkb][2],     sacc[2*kkb][3]));
            ap[2] = h2u(__floats2half2_rn(sacc[2*kkb+1][0],   sacc[2*kkb+1][1]));
            ap[3] = h2u(__floats2half2_rn(sacc[2*kkb+1][2],   sacc[2*kkb+1][3]));
#pragma unroll
            for (int nt = 0; nt < 8; nt++) {
                const uint2 b = *(const uint2*)
                    &VB[kkb * 512 + (nt * 8 + gid) * 8 + tig * 2];
                mma_f16(oacc[nt], ap, (const unsigned*)&b);
            }
        }
    }

    // Epilogue: normalize, write [B,S,D]
    const int r0l = w * 16 + gid;
    const int b = bh >> 4;
    const int h = bh & 15;
    const float inv0 = 1.0f / l0;
    const float inv1 = 1.0f / l1;
#pragma unroll
    for (int nt = 0; nt < 8; nt++) {
        const int col = h * HEAD_DIM + nt * 8 + 2 * tig;
        float2 v0 = make_float2(oacc[nt][0] * inv0, oacc[nt][1] * inv0);
        float2 v1 = make_float2(oacc[nt][2] * inv1, oacc[nt][3] * inv1);
        *(float2*)(AO + (size_t)(b * SEQ + q0 + r0l)     * D_MODEL + col) = v0;
        *(float2*)(AO + (size_t)(b * SEQ + q0 + r0l + 8) * D_MODEL + col) = v1;
    }
}

// ---------------------------------------------------------------------------
extern "C" void kernel_launch(void* const* d_in, const int* in_sizes, int n_in,
                              void* d_out, int out_size)
{
    const float* x  = (const float*)d_in[0];
    const float* wq = (const float*)d_in[1];
    const float* bq = (const float*)d_in[2];
    const float* wk = (const float*)d_in[3];
    const float* bk = (const float*)d_in[4];
    const float* wv = (const float*)d_in[5];
    const float* bv = (const float*)d_in[6];
    const float* wo = (const float*)d_in[7];
    const float* bo = (const float*)d_in[8];

    float *Qp, *Kp, *Vp, *AOp;
    cudaGetSymbolAddress((void**)&Qp,  g_Q);
    cudaGetSymbolAddress((void**)&Kp,  g_K);
    cudaGetSymbolAddress((void**)&Vp,  g_V);
    cudaGetSymbolAddress((void**)&AOp, g_AO);

    const dim3 pg(D_MODEL / 128, MTOT / 128);   // (8, 64)

    gemm_tf32_kernel<true><<<pg, 256>>>(x, wq, bq, Qp);
    gemm_tf32_kernel<true><<<pg, 256>>>(x, wk, bk, Kp);
    gemm_tf32_kernel<true><<<pg, 256>>>(x, wv, bv, Vp);

    cudaFuncSetAttribute(flash_attn_f16_kernel,
                         cudaFuncAttributeMaxDynamicSharedMemorySize, FA_SMEM);
    flash_attn_f16_kernel<<<dim3(SEQ / 128, BATCH * NUM_HEADS), 256, FA_SMEM>>>(Qp, Kp, Vp, AOp);

    gemm_tf32_kernel<false><<<pg, 256>>>(AOp, wo, bo, (float*)d_out);
}

// round 11
// speedup vs baseline: 1.7658x; 1.2102x over previous
#include <cuda_runtime.h>
#include <cuda_fp16.h>

#define D_MODEL   1024
#define NUM_HEADS 16
#define HEAD_DIM  64
#define BATCH     4
#define SEQ       2048
#define MTOT      (BATCH * SEQ)

// Scratch (allocation-free: __device__ globals). 4 x 32 MB.
__device__ float g_Q [MTOT * D_MODEL];
__device__ float g_K [MTOT * D_MODEL];
__device__ float g_V [MTOT * D_MODEL];
__device__ float g_AO[MTOT * D_MODEL];

// ---------------------------------------------------------------------------
// mma helpers
// ---------------------------------------------------------------------------
__device__ __forceinline__ unsigned f2tf32(float x) {
    unsigned u;
    asm("cvt.rna.tf32.f32 %0, %1;" : "=r"(u) : "f"(x));
    return u;
}

__device__ __forceinline__ void mma_tf32(float c[4], const unsigned a[4],
                                         const unsigned b[2]) {
    asm volatile(
        "mma.sync.aligned.m16n8k8.row.col.f32.tf32.tf32.f32 "
        "{%0,%1,%2,%3}, {%4,%5,%6,%7}, {%8,%9}, {%0,%1,%2,%3};"
        : "+f"(c[0]), "+f"(c[1]), "+f"(c[2]), "+f"(c[3])
        : "r"(a[0]), "r"(a[1]), "r"(a[2]), "r"(a[3]), "r"(b[0]), "r"(b[1]));
}

__device__ __forceinline__ void mma_f16(float c[4], const unsigned a[4],
                                        const unsigned b[2]) {
    asm volatile(
        "mma.sync.aligned.m16n8k16.row.col.f32.f16.f16.f32 "
        "{%0,%1,%2,%3}, {%4,%5,%6,%7}, {%8,%9}, {%0,%1,%2,%3};"
        : "+f"(c[0]), "+f"(c[1]), "+f"(c[2]), "+f"(c[3])
        : "r"(a[0]), "r"(a[1]), "r"(a[2]), "r"(a[3]), "r"(b[0]), "r"(b[1]));
}

__device__ __forceinline__ unsigned h2u(__half2 h) {
    return *reinterpret_cast<unsigned*>(&h);
}

// ---------------------------------------------------------------------------
// tf32 tensor-core GEMM (NT) — EXACT R7 version (measured ~171 us each).
// C[M,N] = A[M,K] @ W[N,K]^T + bias[N]
// ---------------------------------------------------------------------------
#define GS 36   // smem row stride (words) for 32 k-columns

template <bool SCATTER>
__global__ __launch_bounds__(256)
void gemm_tf32_kernel(const float* __restrict__ A, const float* __restrict__ W,
                      const float* __restrict__ bias, float* __restrict__ C)
{
    const int K = D_MODEL;
    __shared__ unsigned As[128 * GS];
    __shared__ unsigned Ws[128 * GS];

    const int tid    = threadIdx.x;
    const int wid    = tid >> 5;
    const int lane   = tid & 31;
    const int gid    = lane >> 2;
    const int tig    = lane & 3;
    const int warp_m = wid >> 2;
    const int warp_n = wid & 3;
    const int m0     = blockIdx.y * 128;
    const int n0     = blockIdx.x * 128;

    const int grow = tid >> 1;
    const int gcol = (tid & 1) * 16;
    const float* aptr = A + (size_t)(m0 + grow) * K + gcol;
    const float* wptr = W + (size_t)(n0 + grow) * K + gcol;

    float acc[4][4][4];
#pragma unroll
    for (int i = 0; i < 4; i++)
#pragma unroll
        for (int j = 0; j < 4; j++)
#pragma unroll
            for (int r = 0; r < 4; r++) acc[i][j][r] = 0.f;

    float4 avr[4], wvr[4];
#pragma unroll
    for (int i = 0; i < 4; i++) {
        avr[i] = *(const float4*)(aptr + i * 4);
        wvr[i] = *(const float4*)(wptr + i * 4);
    }

    for (int k0 = 0; k0 < K; k0 += 32) {
        __syncthreads();
#pragma unroll
        for (int i = 0; i < 4; i++) {
            const int c = gcol + i * 4;
            As[grow * GS + c + 0] = f2tf32(avr[i].x);
            As[grow * GS + c + 1] = f2tf32(avr[i].y);
            As[grow * GS + c + 2] = f2tf32(avr[i].z);
            As[grow * GS + c + 3] = f2tf32(avr[i].w);
            Ws[grow * GS + c + 0] = f2tf32(wvr[i].x);
            Ws[grow * GS + c + 1] = f2tf32(wvr[i].y);
            Ws[grow * GS + c + 2] = f2tf32(wvr[i].z);
            Ws[grow * GS + c + 3] = f2tf32(wvr[i].w);
        }
        __syncthreads();

        if (k0 + 32 < K) {
#pragma unroll
            for (int i = 0; i < 4; i++) {
                avr[i] = *(const float4*)(aptr + k0 + 32 + i * 4);
                wvr[i] = *(const float4*)(wptr + k0 + 32 + i * 4);
            }
        }

#pragma unroll
        for (int k8 = 0; k8 < 4; k8++) {
            const int kk = k8 * 8;
            unsigned a[4][4], b[4][2];
#pragma unroll
            for (int mt = 0; mt < 4; mt++) {
                const int m = warp_m * 64 + mt * 16 + gid;
                a[mt][0] = As[(m)     * GS + kk + tig];
                a[mt][1] = As[(m + 8) * GS + kk + tig];
                a[mt][2] = As[(m)     * GS + kk + tig + 4];
                a[mt][3] = As[(m + 8) * GS + kk + tig + 4];
            }
#pragma unroll
            for (int nt = 0; nt < 4; nt++) {
                const int n = warp_n * 32 + nt * 8 + gid;
                b[nt][0] = Ws[n * GS + kk + tig];
                b[nt][1] = Ws[n * GS + kk + tig + 4];
            }
#pragma unroll
            for (int mt = 0; mt < 4; mt++)
#pragma unroll
                for (int nt = 0; nt < 4; nt++)
                    mma_tf32(acc[mt][nt], a[mt], b[nt]);
        }
    }

#pragma unroll
    for (int nt = 0; nt < 4; nt++) {
        const int n  = n0 + warp_n * 32 + nt * 8 + tig * 2;
        const float b0 = bias[n], b1 = bias[n + 1];
#pragma unroll
        for (int mt = 0; mt < 4; mt++) {
            const int m = m0 + warp_m * 64 + mt * 16 + gid;
            float2 v0 = make_float2(acc[mt][nt][0] + b0, acc[mt][nt][1] + b1);
            float2 v1 = make_float2(acc[mt][nt][2] + b0, acc[mt][nt][3] + b1);
            if (SCATTER) {
                const int h  = n >> 6;
                const int hd = n & 63;
                const int bb = m >> 11;
                const int s  = m & (SEQ - 1);
                float* p0 = C + ((size_t)((bb * NUM_HEADS + h) * SEQ + s))     * HEAD_DIM + hd;
                float* p1 = C + ((size_t)((bb * NUM_HEADS + h) * SEQ + s + 8)) * HEAD_DIM + hd;
                *(float2*)p0 = v0;
                *(float2*)p1 = v1;
            } else {
                *(float2*)(C + (size_t)m * D_MODEL + n)       = v0;
                *(float2*)(C + (size_t)(m + 8) * D_MODEL + n) = v1;
            }
        }
    }
}

// ---------------------------------------------------------------------------
// Flash attention v7: fp16 m16n8k16, register-resident P, conflict-audited
// staging, exp2-domain softmax.
//
// K layout: word(p,r) = (p>>3)*1024 + r*8 + (p&3)*2 + ((p>>2)&1), XOR-masked
//   with kmask(q=p>>3) = ((q&1)<<1)|(((q>>1)&1)<<4). Write banks: 32 distinct
//   across the warp (m0..m3,r0 -> bits 2,0,1,4,3). Read mask const per instr.
// V layout: word(n,r) = (r>>4)*512 + n*8 + ((r>>1)&3)*2 + ((r>>3)&1),
//   XOR-masked with vmask(n) = ((n>>2)&15)<<1. Writes <=2-way; reads
//   conflict-free (mask const per 16-lane phase).
// Softmax: Q pre-scaled by HEAD_DIM^-0.5 * log2(e); exp2f throughout.
// ---------------------------------------------------------------------------
#define FA_SMEM ((4096 + 4096) * 4)   // 32,768 B

__global__ __launch_bounds__(256, 1)
void flash_attn_f16_kernel(const float* __restrict__ Q, const float* __restrict__ K,
                           const float* __restrict__ V, float* __restrict__ AO)
{
    extern __shared__ __align__(16) unsigned smu[];
    unsigned* KB = smu;              // 4096 words: [4][128][8]
    unsigned* VB = KB + 4096;        // 4096 words: [8][64][8]

    const int tid  = threadIdx.x;
    const int w    = tid >> 5;
    const int lane = tid & 31;
    const int gid  = lane >> 2;
    const int tig  = lane & 3;
    const int bh   = blockIdx.y;
    const int q0   = blockIdx.x * 128;
    const float qscale = 0.125f * 1.44269504088896340736f;  // Hd^-0.5 * log2e

    const float* Qb = Q + (size_t)bh * SEQ * HEAD_DIM;
    const float* Kb = K + (size_t)bh * SEQ * HEAD_DIM;
    const float* Vb = V + (size_t)bh * SEQ * HEAD_DIM;

    // ---- Q A-fragments in registers (fp16), pre-scaled into log2 domain ----
    unsigned qf[4][4];
    {
        const float* q0p = Qb + (size_t)(q0 + w * 16 + gid) * HEAD_DIM;
        const float* q1p = q0p + 8 * HEAD_DIM;
#pragma unroll
        for (int kkb = 0; kkb < 4; kkb++) {
            const int c = kkb * 16 + 2 * tig;
            float2 x0 = *(const float2*)(q0p + c);
            float2 x1 = *(const float2*)(q1p + c);
            float2 x2 = *(const float2*)(q0p + c + 8);
            float2 x3 = *(const float2*)(q1p + c + 8);
            qf[kkb][0] = h2u(__floats2half2_rn(x0.x * qscale, x0.y * qscale));
            qf[kkb][1] = h2u(__floats2half2_rn(x1.x * qscale, x1.y * qscale));
            qf[kkb][2] = h2u(__floats2half2_rn(x2.x * qscale, x2.y * qscale));
            qf[kkb][3] = h2u(__floats2half2_rn(x3.x * qscale, x3.y * qscale));
        }
    }

    float m0v = -1e30f, m1v = -1e30f, l0 = 0.f, l1 = 0.f;
    float oacc[8][4];
#pragma unroll
    for (int nt = 0; nt < 8; nt++)
#pragma unroll
        for (int r = 0; r < 4; r++) oacc[nt][r] = 0.f;

    for (int kv0 = 0; kv0 < SEQ; kv0 += 128) {
        __syncthreads();   // all warps done reading KB/VB of previous tile

        // ---- K staging: 8 its, 1 LDG.128 + 2 STS.32 (conflict-free) ----
#pragma unroll
        for (int it = 0; it < 8; it++) {
            const int idx = tid + it * 256;
            const int r   = idx >> 4;            // kv row 0..127
            const int c4  = (idx & 15) * 4;      // k col, 4-aligned
            const float4 kv4 = *(const float4*)(Kb + (size_t)(kv0 + r) * HEAD_DIM + c4);
            const int p0   = c4 >> 1;            // even half2-pair index
            const int q    = p0 >> 3;
            const int km   = ((q & 1) << 1) | (((q >> 1) & 1) << 4);
            const int w0   = q * 1024 + r * 8 + (p0 & 3) * 2 + ((p0 >> 2) & 1);
            const int p1   = p0 + 1;             // same q (p0 even)
            const int w1   = q * 1024 + r * 8 + (p1 & 3) * 2 + ((p1 >> 2) & 1);
            KB[w0 ^ km] = h2u(__floats2half2_rn(kv4.x, kv4.y));
            KB[w1 ^ km] = h2u(__floats2half2_rn(kv4.z, kv4.w));
        }

        // ---- V staging: 8 its, 2 LDG.64 + 2 STS.32 (<=2-way) ----
#pragma unroll
        for (int it = 0; it < 8; it++) {
            const int idx = tid + it * 256;      // unit = 2 kv rows x 2 cols
            const int rp  = idx >> 5;            // 0..63
            const int cp  = idx & 31;            // 0..31
            const int r   = rp * 2;
            const int c   = cp * 2;
            const float2 f0 = *(const float2*)(Vb + (size_t)(kv0 + r)     * HEAD_DIM + c);
            const float2 f1 = *(const float2*)(Vb + (size_t)(kv0 + r + 1) * HEAD_DIM + c);
            const int base = (rp >> 3) * 512 + (rp & 3) * 2 + ((rp >> 2) & 1);
            const int n0i  = c;
            const int n1i  = c + 1;
            const int vm0  = ((n0i >> 2) & 15) << 1;
            const int vm1  = ((n1i >> 2) & 15) << 1;
            VB[(base + n0i * 8) ^ vm0] = h2u(__floats2half2_rn(f0.x, f1.x));
            VB[(base + n1i * 8) ^ vm1] = h2u(__floats2half2_rn(f0.y, f1.y));
        }
        __syncthreads();

        // ---- S = Q K^T : 4 k-blocks x 16 n-tiles of m16n8k16 ----
        float sacc[16][4];
#pragma unroll
        for (int nt = 0; nt < 16; nt++)
#pragma unroll
            for (int r = 0; r < 4; r++) sacc[nt][r] = 0.f;

#pragma unroll
        for (int kkb = 0; kkb < 4; kkb++) {
            const int km = ((kkb & 1) << 1) | (((kkb >> 1) & 1) << 4);
#pragma unroll
            for (int nt = 0; nt < 16; nt++) {
                const uint2 b = *(const uint2*)
                    &KB[(kkb * 1024 + (nt * 8 + gid) * 8 + tig * 2) ^ km];
                mma_f16(sacc[nt], qf[kkb], (const unsigned*)&b);
            }
        }

        // ---- online softmax in log2 domain (fp32) ----
        float rm0 = -1e30f, rm1 = -1e30f;
#pragma unroll
        for (int nt = 0; nt < 16; nt++) {
            rm0 = fmaxf(rm0, fmaxf(sacc[nt][0], sacc[nt][1]));
            rm1 = fmaxf(rm1, fmaxf(sacc[nt][2], sacc[nt][3]));
        }
        rm0 = fmaxf(rm0, __shfl_xor_sync(0xffffffffu, rm0, 1));
        rm0 = fmaxf(rm0, __shfl_xor_sync(0xffffffffu, rm0, 2));
        rm1 = fmaxf(rm1, __shfl_xor_sync(0xffffffffu, rm1, 1));
        rm1 = fmaxf(rm1, __shfl_xor_sync(0xffffffffu, rm1, 2));

        const float mn0 = fmaxf(m0v, rm0);
        const float mn1 = fmaxf(m1v, rm1);
        const float al0 = exp2f(m0v - mn0);
        const float al1 = exp2f(m1v - mn1);
        m0v = mn0; m1v = mn1;

        float rs0 = 0.f, rs1 = 0.f;
#pragma unroll
        for (int nt = 0; nt < 16; nt++) {
            sacc[nt][0] = exp2f(sacc[nt][0] - mn0);
            sacc[nt][1] = exp2f(sacc[nt][1] - mn0);
            sacc[nt][2] = exp2f(sacc[nt][2] - mn1);
            sacc[nt][3] = exp2f(sacc[nt][3] - mn1);
            rs0 += sacc[nt][0] + sacc[nt][1];
            rs1 += sacc[nt][2] + sacc[nt][3];
        }
        rs0 += __shfl_xor_sync(0xffffffffu, rs0, 1);
        rs0 += __shfl_xor_sync(0xffffffffu, rs0, 2);
        rs1 += __shfl_xor_sync(0xffffffffu, rs1, 1);
        rs1 += __shfl_xor_sync(0xffffffffu, rs1, 2);
        l0 = l0 * al0 + rs0;
        l1 = l1 * al1 + rs1;

#pragma unroll
        for (int nt = 0; nt < 8; nt++) {
            oacc[nt][0] *= al0; oacc[nt][1] *= al0;
            oacc[nt][2] *= al1; oacc[nt][3] *= al1;
        }

        // ---- O += P V : P from registers (C->A fragment identity) ----
#pragma unroll
        for (int kkb = 0; kkb < 8; kkb++) {
            unsigned ap[4];
            ap[0] = h2u(__floats2half2_rn(sacc[2*kkb][0],   sacc[2*kkb][1]));
            ap[1] = h2u(__floats2half2_rn(sacc[2*kkb][2],   sacc[2*kkb][3]));
            ap[2] = h2u(__floats2half2_rn(sacc[2*kkb+1][0], sacc[2*kkb+1][1]));
            ap[3] = h2u(__floats2half2_rn(sacc[2*kkb+1][2], sacc[2*kkb+1][3]));
#pragma unroll
            for (int nt = 0; nt < 8; nt++) {
                const int n  = nt * 8 + gid;
                const int vm = (((n >> 2) & 15) << 1);
                const uint2 b = *(const uint2*)
                    &VB[(kkb * 512 + n * 8 + tig * 2) ^ vm];
                mma_f16(oacc[nt], ap, (const unsigned*)&b);
            }
        }
    }

    // Epilogue: normalize, write [B,S,D]
    const int r0l = w * 16 + gid;
    const int b = bh >> 4;
    const int h = bh & 15;
    const float inv0 = 1.0f / l0;
    const float inv1 = 1.0f / l1;
#pragma unroll
    for (int nt = 0; nt < 8; nt++) {
        const int col = h * HEAD_DIM + nt * 8 + 2 * tig;
        float2 v0 = make_float2(oacc[nt][0] * inv0, oacc[nt][1] * inv0);
        float2 v1 = make_float2(oacc[nt][2] * inv1, oacc[nt][3] * inv1);
        *(float2*)(AO + (size_t)(b * SEQ + q0 + r0l)     * D_MODEL + col) = v0;
        *(float2*)(AO + (size_t)(b * SEQ + q0 + r0l + 8) * D_MODEL + col) = v1;
    }
}

// ---------------------------------------------------------------------------
extern "C" void kernel_launch(void* const* d_in, const int* in_sizes, int n_in,
                              void* d_out, int out_size)
{
    const float* x  = (const float*)d_in[0];
    const float* wq = (const float*)d_in[1];
    const float* bq = (const float*)d_in[2];
    const float* wk = (const float*)d_in[3];
    const float* bk = (const float*)d_in[4];
    const float* wv = (const float*)d_in[5];
    const float* bv = (const float*)d_in[6];
    const float* wo = (const float*)d_in[7];
    const float* bo = (const float*)d_in[8];

    float *Qp, *Kp, *Vp, *AOp;
    cudaGetSymbolAddress((void**)&Qp,  g_Q);
    cudaGetSymbolAddress((void**)&Kp,  g_K);
    cudaGetSymbolAddress((void**)&Vp,  g_V);
    cudaGetSymbolAddress((void**)&AOp, g_AO);

    const dim3 pg(D_MODEL / 128, MTOT / 128);   // (8, 64)

    gemm_tf32_kernel<true><<<pg, 256>>>(x, wq, bq, Qp);
    gemm_tf32_kernel<true><<<pg, 256>>>(x, wk, bk, Kp);
    gemm_tf32_kernel<true><<<pg, 256>>>(x, wv, bv, Vp);

    cudaFuncSetAttribute(flash_attn_f16_kernel,
                         cudaFuncAttributeMaxDynamicSharedMemorySize, FA_SMEM);
    flash_attn_f16_kernel<<<dim3(SEQ / 128, BATCH * NUM_HEADS), 256, FA_SMEM>>>(Qp, Kp, Vp, AOp);

    gemm_tf32_kernel<false><<<pg, 256>>>(AOp, wo, bo, (float*)d_out);
}

// round 12
// speedup vs baseline: 2.2507x; 1.2746x over previous
#include <cuda_runtime.h>
#include <cuda_fp16.h>

#define D_MODEL   1024
#define NUM_HEADS 16
#define HEAD_DIM  64
#define BATCH     4
#define SEQ       2048
#define MTOT      (BATCH * SEQ)

// Scratch (allocation-free: __device__ globals). 4 x 32 MB.
__device__ float g_Q [MTOT * D_MODEL];
__device__ float g_K [MTOT * D_MODEL];
__device__ float g_V [MTOT * D_MODEL];
__device__ float g_AO[MTOT * D_MODEL];

// ---------------------------------------------------------------------------
// fp16 mma helper (fragment layout validated in R10/R11 flash kernel)
// ---------------------------------------------------------------------------
__device__ __forceinline__ void mma_f16(float c[4], const unsigned a[4],
                                        const unsigned b[2]) {
    asm volatile(
        "mma.sync.aligned.m16n8k16.row.col.f32.f16.f16.f32 "
        "{%0,%1,%2,%3}, {%4,%5,%6,%7}, {%8,%9}, {%0,%1,%2,%3};"
        : "+f"(c[0]), "+f"(c[1]), "+f"(c[2]), "+f"(c[3])
        : "r"(a[0]), "r"(a[1]), "r"(a[2]), "r"(a[3]), "r"(b[0]), "r"(b[1]));
}

__device__ __forceinline__ unsigned h2u(__half2 h) {
    return *reinterpret_cast<unsigned*>(&h);
}

// ---------------------------------------------------------------------------
// fp16 tensor-core GEMM (NT): C[M,N] = A[M,K] @ W[N,K]^T + bias[N]
// fp16 operands (same 10-bit mantissa as tf32 -> same rounding), fp32 accum.
// Block 128x128, BK=32 (2 x k16 blocks), 8 warps (2m x 4n), warp 64x32.
//
// Packed smem layout (identical to flash K layout, q = k16-block index):
//   half2 pair p (k = 2p, 2p+1) of row r lives at word
//     q*1024 + r*8 + (p&3)*2 + ((p>>2)&1),  XOR-masked with km = q<<1.
//   B-fragment  = one LDS.64 at q*1024 + n*8 + tig*2  (^km)
//   A-fragment  = two LDS.64 (rows r, r+8)            (^km)
// Staging: thread owns 4 float4 slots (r = tid>>3 + 32*it, c = (tid&7)*4);
// per-instruction write banks audited: all 32 distinct (conflict-free).
// ---------------------------------------------------------------------------
template <bool SCATTER>
__global__ __launch_bounds__(256)
void gemm_f16_kernel(const float* __restrict__ A, const float* __restrict__ W,
                     const float* __restrict__ bias, float* __restrict__ C)
{
    const int K = D_MODEL;
    __shared__ __align__(16) unsigned As[2048];   // 8 KB
    __shared__ __align__(16) unsigned Ws[2048];   // 8 KB

    const int tid    = threadIdx.x;
    const int wid    = tid >> 5;
    const int lane   = tid & 31;
    const int gid    = lane >> 2;
    const int tig    = lane & 3;
    const int warp_m = wid >> 2;
    const int warp_n = wid & 3;
    const int m0     = blockIdx.y * 128;
    const int n0     = blockIdx.x * 128;

    // staging geometry: slot it -> row r_base + 32*it, cols cc..cc+3
    const int r_base = tid >> 3;          // 0..31
    const int cc     = (tid & 7) * 4;     // 0..28
    const float* aptr = A + (size_t)(m0 + r_base) * K + cc;
    const float* wptr = W + (size_t)(n0 + r_base) * K + cc;

    const int p0   = cc >> 1;             // even half2-pair index
    const int q    = p0 >> 3;             // 0 or 1
    const int km_w = q << 1;
    const int off0 = (p0 & 3) * 2 + ((p0 >> 2) & 1);
    const int off1 = ((p0 + 1) & 3) * 2 + (((p0 + 1) >> 2) & 1);
    const int wbase = q * 1024;

    float acc[4][4][4];
#pragma unroll
    for (int i = 0; i < 4; i++)
#pragma unroll
        for (int j = 0; j < 4; j++)
#pragma unroll
            for (int r = 0; r < 4; r++) acc[i][j][r] = 0.f;

    float4 avr[4], wvr[4];
#pragma unroll
    for (int it = 0; it < 4; it++) {
        avr[it] = *(const float4*)(aptr + (size_t)it * 32 * K);
        wvr[it] = *(const float4*)(wptr + (size_t)it * 32 * K);
    }

    for (int k0 = 0; k0 < K; k0 += 32) {
        __syncthreads();
#pragma unroll
        for (int it = 0; it < 4; it++) {
            const int base = wbase + (r_base + it * 32) * 8;
            As[(base + off0) ^ km_w] = h2u(__floats2half2_rn(avr[it].x, avr[it].y));
            As[(base + off1) ^ km_w] = h2u(__floats2half2_rn(avr[it].z, avr[it].w));
            Ws[(base + off0) ^ km_w] = h2u(__floats2half2_rn(wvr[it].x, wvr[it].y));
            Ws[(base + off1) ^ km_w] = h2u(__floats2half2_rn(wvr[it].z, wvr[it].w));
        }
        __syncthreads();

        if (k0 + 32 < K) {    // prefetch next K-tile into registers
#pragma unroll
            for (int it = 0; it < 4; it++) {
                avr[it] = *(const float4*)(aptr + (size_t)it * 32 * K + k0 + 32);
                wvr[it] = *(const float4*)(wptr + (size_t)it * 32 * K + k0 + 32);
            }
        }

#pragma unroll
        for (int q8 = 0; q8 < 2; q8++) {
            const int km = q8 << 1;
            const int qb = q8 * 1024;
            unsigned af[4][4];
            uint2    bf[4];
#pragma unroll
            for (int mt = 0; mt < 4; mt++) {
                const int r = warp_m * 64 + mt * 16 + gid;
                const uint2 lo = *(const uint2*)&As[(qb + r * 8 + tig * 2) ^ km];
                const uint2 hi = *(const uint2*)&As[(qb + (r + 8) * 8 + tig * 2) ^ km];
                af[mt][0] = lo.x; af[mt][1] = hi.x;
                af[mt][2] = lo.y; af[mt][3] = hi.y;
            }
#pragma unroll
            for (int nt = 0; nt < 4; nt++) {
                const int n = warp_n * 32 + nt * 8 + gid;
                bf[nt] = *(const uint2*)&Ws[(qb + n * 8 + tig * 2) ^ km];
            }
#pragma unroll
            for (int mt = 0; mt < 4; mt++)
#pragma unroll
                for (int nt = 0; nt < 4; nt++)
                    mma_f16(acc[mt][nt], af[mt], (const unsigned*)&bf[nt]);
        }
    }

    // Epilogue (same fragment->C mapping as validated R7 GEMM)
#pragma unroll
    for (int nt = 0; nt < 4; nt++) {
        const int n  = n0 + warp_n * 32 + nt * 8 + tig * 2;
        const float b0 = bias[n], b1 = bias[n + 1];
#pragma unroll
        for (int mt = 0; mt < 4; mt++) {
            const int m = m0 + warp_m * 64 + mt * 16 + gid;
            float2 v0 = make_float2(acc[mt][nt][0] + b0, acc[mt][nt][1] + b1);
            float2 v1 = make_float2(acc[mt][nt][2] + b0, acc[mt][nt][3] + b1);
            if (SCATTER) {
                const int h  = n >> 6;
                const int hd = n & 63;
                const int bb = m >> 11;
                const int s  = m & (SEQ - 1);
                float* p0c = C + ((size_t)((bb * NUM_HEADS + h) * SEQ + s))     * HEAD_DIM + hd;
                float* p1c = C + ((size_t)((bb * NUM_HEADS + h) * SEQ + s + 8)) * HEAD_DIM + hd;
                *(float2*)p0c = v0;
                *(float2*)p1c = v1;
            } else {
                *(float2*)(C + (size_t)m * D_MODEL + n)       = v0;
                *(float2*)(C + (size_t)(m + 8) * D_MODEL + n) = v1;
            }
        }
    }
}

// ---------------------------------------------------------------------------
// Flash attention v7 (unchanged from R11: 354 us, conflict-audited staging,
// register-resident P, exp2-domain softmax).
// ---------------------------------------------------------------------------
#define FA_SMEM ((4096 + 4096) * 4)   // 32,768 B

__global__ __launch_bounds__(256, 1)
void flash_attn_f16_kernel(const float* __restrict__ Q, const float* __restrict__ K,
                           const float* __restrict__ V, float* __restrict__ AO)
{
    extern __shared__ __align__(16) unsigned smu[];
    unsigned* KB = smu;              // 4096 words: [4][128][8]
    unsigned* VB = KB + 4096;        // 4096 words: [8][64][8]

    const int tid  = threadIdx.x;
    const int w    = tid >> 5;
    const int lane = tid & 31;
    const int gid  = lane >> 2;
    const int tig  = lane & 3;
    const int bh   = blockIdx.y;
    const int q0   = blockIdx.x * 128;
    const float qscale = 0.125f * 1.44269504088896340736f;  // Hd^-0.5 * log2e

    const float* Qb = Q + (size_t)bh * SEQ * HEAD_DIM;
    const float* Kb = K + (size_t)bh * SEQ * HEAD_DIM;
    const float* Vb = V + (size_t)bh * SEQ * HEAD_DIM;

    // ---- Q A-fragments in registers (fp16), pre-scaled into log2 domain ----
    unsigned qf[4][4];
    {
        const float* q0p = Qb + (size_t)(q0 + w * 16 + gid) * HEAD_DIM;
        const float* q1p = q0p + 8 * HEAD_DIM;
#pragma unroll
        for (int kkb = 0; kkb < 4; kkb++) {
            const int c = kkb * 16 + 2 * tig;
            float2 x0 = *(const float2*)(q0p + c);
            float2 x1 = *(const float2*)(q1p + c);
            float2 x2 = *(const float2*)(q0p + c + 8);
            float2 x3 = *(const float2*)(q1p + c + 8);
            qf[kkb][0] = h2u(__floats2half2_rn(x0.x * qscale, x0.y * qscale));
            qf[kkb][1] = h2u(__floats2half2_rn(x1.x * qscale, x1.y * qscale));
            qf[kkb][2] = h2u(__floats2half2_rn(x2.x * qscale, x2.y * qscale));
            qf[kkb][3] = h2u(__floats2half2_rn(x3.x * qscale, x3.y * qscale));
        }
    }

    float m0v = -1e30f, m1v = -1e30f, l0 = 0.f, l1 = 0.f;
    float oacc[8][4];
#pragma unroll
    for (int nt = 0; nt < 8; nt++)
#pragma unroll
        for (int r = 0; r < 4; r++) oacc[nt][r] = 0.f;

    for (int kv0 = 0; kv0 < SEQ; kv0 += 128) {
        __syncthreads();   // all warps done reading KB/VB of previous tile

        // ---- K staging: 8 its, 1 LDG.128 + 2 STS.32 (conflict-free) ----
#pragma unroll
        for (int it = 0; it < 8; it++) {
            const int idx = tid + it * 256;
            const int r   = idx >> 4;            // kv row 0..127
            const int c4  = (idx & 15) * 4;      // k col, 4-aligned
            const float4 kv4 = *(const float4*)(Kb + (size_t)(kv0 + r) * HEAD_DIM + c4);
            const int p0   = c4 >> 1;
            const int q    = p0 >> 3;
            const int km   = ((q & 1) << 1) | (((q >> 1) & 1) << 4);
            const int w0   = q * 1024 + r * 8 + (p0 & 3) * 2 + ((p0 >> 2) & 1);
            const int p1   = p0 + 1;
            const int w1   = q * 1024 + r * 8 + (p1 & 3) * 2 + ((p1 >> 2) & 1);
            KB[w0 ^ km] = h2u(__floats2half2_rn(kv4.x, kv4.y));
            KB[w1 ^ km] = h2u(__floats2half2_rn(kv4.z, kv4.w));
        }

        // ---- V staging: 8 its, 2 LDG.64 + 2 STS.32 (<=2-way) ----
#pragma unroll
        for (int it = 0; it < 8; it++) {
            const int idx = tid + it * 256;      // unit = 2 kv rows x 2 cols
            const int rp  = idx >> 5;            // 0..63
            const int cp  = idx & 31;            // 0..31
            const int r   = rp * 2;
            const int c   = cp * 2;
            const float2 f0 = *(const float2*)(Vb + (size_t)(kv0 + r)     * HEAD_DIM + c);
            const float2 f1 = *(const float2*)(Vb + (size_t)(kv0 + r + 1) * HEAD_DIM + c);
            const int base = (rp >> 3) * 512 + (rp & 3) * 2 + ((rp >> 2) & 1);
            const int n0i  = c;
            const int n1i  = c + 1;
            const int vm0  = ((n0i >> 2) & 15) << 1;
            const int vm1  = ((n1i >> 2) & 15) << 1;
            VB[(base + n0i * 8) ^ vm0] = h2u(__floats2half2_rn(f0.x, f1.x));
            VB[(base + n1i * 8) ^ vm1] = h2u(__floats2half2_rn(f0.y, f1.y));
        }
        __syncthreads();

        // ---- S = Q K^T : 4 k-blocks x 16 n-tiles of m16n8k16 ----
        float sacc[16][4];
#pragma unroll
        for (int nt = 0; nt < 16; nt++)
#pragma unroll
            for (int r = 0; r < 4; r++) sacc[nt][r] = 0.f;

#pragma unroll
        for (int kkb = 0; kkb < 4; kkb++) {
            const int km = ((kkb & 1) << 1) | (((kkb >> 1) & 1) << 4);
#pragma unroll
            for (int nt = 0; nt < 16; nt++) {
                const uint2 b = *(const uint2*)
                    &KB[(kkb * 1024 + (nt * 8 + gid) * 8 + tig * 2) ^ km];
                mma_f16(sacc[nt], qf[kkb], (const unsigned*)&b);
            }
        }

        // ---- online softmax in log2 domain (fp32) ----
        float rm0 = -1e30f, rm1 = -1e30f;
#pragma unroll
        for (int nt = 0; nt < 16; nt++) {
            rm0 = fmaxf(rm0, fmaxf(sacc[nt][0], sacc[nt][1]));
            rm1 = fmaxf(rm1, fmaxf(sacc[nt][2], sacc[nt][3]));
        }
        rm0 = fmaxf(rm0, __shfl_xor_sync(0xffffffffu, rm0, 1));
        rm0 = fmaxf(rm0, __shfl_xor_sync(0xffffffffu, rm0, 2));
        rm1 = fmaxf(rm1, __shfl_xor_sync(0xffffffffu, rm1, 1));
        rm1 = fmaxf(rm1, __shfl_xor_sync(0xffffffffu, rm1, 2));

        const float mn0 = fmaxf(m0v, rm0);
        const float mn1 = fmaxf(m1v, rm1);
        const float al0 = exp2f(m0v - mn0);
        const float al1 = exp2f(m1v - mn1);
        m0v = mn0; m1v = mn1;

        float rs0 = 0.f, rs1 = 0.f;
#pragma unroll
        for (int nt = 0; nt < 16; nt++) {
            sacc[nt][0] = exp2f(sacc[nt][0] - mn0);
            sacc[nt][1] = exp2f(sacc[nt][1] - mn0);
            sacc[nt][2] = exp2f(sacc[nt][2] - mn1);
            sacc[nt][3] = exp2f(sacc[nt][3] - mn1);
            rs0 += sacc[nt][0] + sacc[nt][1];
            rs1 += sacc[nt][2] + sacc[nt][3];
        }
        rs0 += __shfl_xor_sync(0xffffffffu, rs0, 1);
        rs0 += __shfl_xor_sync(0xffffffffu, rs0, 2);
        rs1 += __shfl_xor_sync(0xffffffffu, rs1, 1);
        rs1 += __shfl_xor_sync(0xffffffffu, rs1, 2);
        l0 = l0 * al0 + rs0;
        l1 = l1 * al1 + rs1;

#pragma unroll
        for (int nt = 0; nt < 8; nt++) {
            oacc[nt][0] *= al0; oacc[nt][1] *= al0;
            oacc[nt][2] *= al1; oacc[nt][3] *= al1;
        }

        // ---- O += P V : P from registers (C->A fragment identity) ----
#pragma unroll
        for (int kkb = 0; kkb < 8; kkb++) {
            unsigned ap[4];
            ap[0] = h2u(__floats2half2_rn(sacc[2*kkb][0],   sacc[2*kkb][1]));
            ap[1] = h2u(__floats2half2_rn(sacc[2*kkb][2],   sacc[2*kkb][3]));
            ap[2] = h2u(__floats2half2_rn(sacc[2*kkb+1][0], sacc[2*kkb+1][1]));
            ap[3] = h2u(__floats2half2_rn(sacc[2*kkb+1][2], sacc[2*kkb+1][3]));
#pragma unroll
            for (int nt = 0; nt < 8; nt++) {
                const int n  = nt * 8 + gid;
                const int vm = (((n >> 2) & 15) << 1);
                const uint2 b = *(const uint2*)
                    &VB[(kkb * 512 + n * 8 + tig * 2) ^ vm];
                mma_f16(oacc[nt], ap, (const unsigned*)&b);
            }
        }
    }

    // Epilogue: normalize, write [B,S,D]
    const int r0l = w * 16 + gid;
    const int b = bh >> 4;
    const int h = bh & 15;
    const float inv0 = 1.0f / l0;
    const float inv1 = 1.0f / l1;
#pragma unroll
    for (int nt = 0; nt < 8; nt++) {
        const int col = h * HEAD_DIM + nt * 8 + 2 * tig;
        float2 v0 = make_float2(oacc[nt][0] * inv0, oacc[nt][1] * inv0);
        float2 v1 = make_float2(oacc[nt][2] * inv1, oacc[nt][3] * inv1);
        *(float2*)(AO + (size_t)(b * SEQ + q0 + r0l)     * D_MODEL + col) = v0;
        *(float2*)(AO + (size_t)(b * SEQ + q0 + r0l + 8) * D_MODEL + col) = v1;
    }
}

// ---------------------------------------------------------------------------
extern "C" void kernel_launch(void* const* d_in, const int* in_sizes, int n_in,
                              void* d_out, int out_size)
{
    const float* x  = (const float*)d_in[0];
    const float* wq = (const float*)d_in[1];
    const float* bq = (const float*)d_in[2];
    const float* wk = (const float*)d_in[3];
    const float* bk = (const float*)d_in[4];
    const float* wv = (const float*)d_in[5];
    const float* bv = (const float*)d_in[6];
    const float* wo = (const float*)d_in[7];
    const float* bo = (const float*)d_in[8];

    float *Qp, *Kp, *Vp, *AOp;
    cudaGetSymbolAddress((void**)&Qp,  g_Q);
    cudaGetSymbolAddress((void**)&Kp,  g_K);
    cudaGetSymbolAddress((void**)&Vp,  g_V);
    cudaGetSymbolAddress((void**)&AOp, g_AO);

    const dim3 pg(D_MODEL / 128, MTOT / 128);   // (8, 64)

    gemm_f16_kernel<true><<<pg, 256>>>(x, wq, bq, Qp);
    gemm_f16_kernel<true><<<pg, 256>>>(x, wk, bk, Kp);
    gemm_f16_kernel<true><<<pg, 256>>>(x, wv, bv, Vp);

    cudaFuncSetAttribute(flash_attn_f16_kernel,
                         cudaFuncAttributeMaxDynamicSharedMemorySize, FA_SMEM);
    flash_attn_f16_kernel<<<dim3(SEQ / 128, BATCH * NUM_HEADS), 256, FA_SMEM>>>(Qp, Kp, Vp, AOp);

    gemm_f16_kernel<false><<<pg, 256>>>(AOp, wo, bo, (float*)d_out);
}

// round 14
// speedup vs baseline: 2.8710x; 1.2756x over previous
#include <cuda_runtime.h>
#include <cuda_fp16.h>
#include <cstdint>

#define D_MODEL   1024
#define NUM_HEADS 16
#define HEAD_DIM  64
#define BATCH     4
#define SEQ       2048
#define MTOT      (BATCH * SEQ)

// Scratch (allocation-free: __device__ globals). Q/K/V fp16, AO fp32.
__device__ __half g_Q [MTOT * D_MODEL];
__device__ __half g_K [MTOT * D_MODEL];
__device__ __half g_V [MTOT * D_MODEL];
__device__ float  g_AO[MTOT * D_MODEL];

// ---------------------------------------------------------------------------
// helpers
// ---------------------------------------------------------------------------
__device__ __forceinline__ void mma_f16(float c[4], const unsigned a[4],
                                        const unsigned b[2]) {
    asm volatile(
        "mma.sync.aligned.m16n8k16.row.col.f32.f16.f16.f32 "
        "{%0,%1,%2,%3}, {%4,%5,%6,%7}, {%8,%9}, {%0,%1,%2,%3};"
        : "+f"(c[0]), "+f"(c[1]), "+f"(c[2]), "+f"(c[3])
        : "r"(a[0]), "r"(a[1]), "r"(a[2]), "r"(a[3]), "r"(b[0]), "r"(b[1]));
}

__device__ __forceinline__ unsigned h2u(__half2 h) {
    return *reinterpret_cast<unsigned*>(&h);
}

__device__ __forceinline__ void ldsm_x4(unsigned r[4], uint32_t a) {
    asm volatile("ldmatrix.sync.aligned.m8n8.x4.shared.b16 {%0,%1,%2,%3}, [%4];"
        : "=r"(r[0]), "=r"(r[1]), "=r"(r[2]), "=r"(r[3]) : "r"(a));
}
__device__ __forceinline__ void ldsm_x4_t(unsigned r[4], uint32_t a) {
    asm volatile("ldmatrix.sync.aligned.m8n8.x4.trans.shared.b16 {%0,%1,%2,%3}, [%4];"
        : "=r"(r[0]), "=r"(r[1]), "=r"(r[2]), "=r"(r[3]) : "r"(a));
}
__device__ __forceinline__ void cp16(uint32_t dst, const void* src) {
    asm volatile("cp.async.cg.shared.global [%0], [%1], 16;" :: "r"(dst), "l"(src));
}

// ---------------------------------------------------------------------------
// fp16 tensor-core GEMM (NT) — R12 version; epilogue writes __half when
// SCATTER (Q/K/V scratch), float otherwise (d_out).
// ---------------------------------------------------------------------------
template <bool SCATTER>
__global__ __launch_bounds__(256)
void gemm_f16_kernel(const float* __restrict__ A, const float* __restrict__ W,
                     const float* __restrict__ bias, void* __restrict__ Cv)
{
    const int K = D_MODEL;
    __shared__ __align__(16) unsigned As[2048];
    __shared__ __align__(16) unsigned Ws[2048];

    const int tid    = threadIdx.x;
    const int wid    = tid >> 5;
    const int lane   = tid & 31;
    const int gid    = lane >> 2;
    const int tig    = lane & 3;
    const int warp_m = wid >> 2;
    const int warp_n = wid & 3;
    const int m0     = blockIdx.y * 128;
    const int n0     = blockIdx.x * 128;

    const int r_base = tid >> 3;
    const int cc     = (tid & 7) * 4;
    const float* aptr = A + (size_t)(m0 + r_base) * K + cc;
    const float* wptr = W + (size_t)(n0 + r_base) * K + cc;

    const int p0   = cc >> 1;
    const int q    = p0 >> 3;
    const int km_w = q << 1;
    const int off0 = (p0 & 3) * 2 + ((p0 >> 2) & 1);
    const int off1 = ((p0 + 1) & 3) * 2 + (((p0 + 1) >> 2) & 1);
    const int wbase = q * 1024;

    float acc[4][4][4];
#pragma unroll
    for (int i = 0; i < 4; i++)
#pragma unroll
        for (int j = 0; j < 4; j++)
#pragma unroll
            for (int r = 0; r < 4; r++) acc[i][j][r] = 0.f;

    float4 avr[4], wvr[4];
#pragma unroll
    for (int it = 0; it < 4; it++) {
        avr[it] = *(const float4*)(aptr + (size_t)it * 32 * K);
        wvr[it] = *(const float4*)(wptr + (size_t)it * 32 * K);
    }

    for (int k0 = 0; k0 < K; k0 += 32) {
        __syncthreads();
#pragma unroll
        for (int it = 0; it < 4; it++) {
            const int base = wbase + (r_base + it * 32) * 8;
            As[(base + off0) ^ km_w] = h2u(__floats2half2_rn(avr[it].x, avr[it].y));
            As[(base + off1) ^ km_w] = h2u(__floats2half2_rn(avr[it].z, avr[it].w));
            Ws[(base + off0) ^ km_w] = h2u(__floats2half2_rn(wvr[it].x, wvr[it].y));
            Ws[(base + off1) ^ km_w] = h2u(__floats2half2_rn(wvr[it].z, wvr[it].w));
        }
        __syncthreads();

        if (k0 + 32 < K) {
#pragma unroll
            for (int it = 0; it < 4; it++) {
                avr[it] = *(const float4*)(aptr + (size_t)it * 32 * K + k0 + 32);
                wvr[it] = *(const float4*)(wptr + (size_t)it * 32 * K + k0 + 32);
            }
        }

#pragma unroll
        for (int q8 = 0; q8 < 2; q8++) {
            const int km = q8 << 1;
            const int qb = q8 * 1024;
            unsigned af[4][4];
            uint2    bf[4];
#pragma unroll
            for (int mt = 0; mt < 4; mt++) {
                const int r = warp_m * 64 + mt * 16 + gid;
                const uint2 lo = *(const uint2*)&As[(qb + r * 8 + tig * 2) ^ km];
                const uint2 hi = *(const uint2*)&As[(qb + (r + 8) * 8 + tig * 2) ^ km];
                af[mt][0] = lo.x; af[mt][1] = hi.x;
                af[mt][2] = lo.y; af[mt][3] = hi.y;
            }
#pragma unroll
            for (int nt = 0; nt < 4; nt++) {
                const int n = warp_n * 32 + nt * 8 + gid;
                bf[nt] = *(const uint2*)&Ws[(qb + n * 8 + tig * 2) ^ km];
            }
#pragma unroll
            for (int mt = 0; mt < 4; mt++)
#pragma unroll
                for (int nt = 0; nt < 4; nt++)
                    mma_f16(acc[mt][nt], af[mt], (const unsigned*)&bf[nt]);
        }
    }

#pragma unroll
    for (int nt = 0; nt < 4; nt++) {
        const int n  = n0 + warp_n * 32 + nt * 8 + tig * 2;
        const float b0 = bias[n], b1 = bias[n + 1];
#pragma unroll
        for (int mt = 0; mt < 4; mt++) {
            const int m = m0 + warp_m * 64 + mt * 16 + gid;
            if (SCATTER) {
                __half* Ch = (__half*)Cv;
                const int h  = n >> 6;
                const int hd = n & 63;
                const int bb = m >> 11;
                const int s  = m & (SEQ - 1);
                unsigned u0 = h2u(__floats2half2_rn(acc[mt][nt][0] + b0,
                                                    acc[mt][nt][1] + b1));
                unsigned u1 = h2u(__floats2half2_rn(acc[mt][nt][2] + b0,
                                                    acc[mt][nt][3] + b1));
                *(unsigned*)(Ch + ((size_t)((bb * NUM_HEADS + h) * SEQ + s))     * HEAD_DIM + hd) = u0;
                *(unsigned*)(Ch + ((size_t)((bb * NUM_HEADS + h) * SEQ + s + 8)) * HEAD_DIM + hd) = u1;
            } else {
                float* Cf = (float*)Cv;
                float2 v0 = make_float2(acc[mt][nt][0] + b0, acc[mt][nt][1] + b1);
                float2 v1 = make_float2(acc[mt][nt][2] + b0, acc[mt][nt][3] + b1);
                *(float2*)(Cf + (size_t)m * D_MODEL + n)       = v0;
                *(float2*)(Cf + (size_t)(m + 8) * D_MODEL + n) = v1;
            }
        }
    }
}

// ---------------------------------------------------------------------------
// Flash attention v8: cp.async double-buffered K/V (fp16, row-major,
// chunk-XOR swizzle), ldmatrix fragments, register-resident P, exp2 softmax.
// Br = Bc = 128, Hd = 64, 8 warps; warp w owns S rows [16w, 16w+16).
//
// smem: 2 buffers x (K 16KB + V 16KB) = 64 KB. Tile i+1 streams via cp.async
// while tile i computes -> gmem latency off the critical path.
// K/V row r, 16B chunk c stored at chunk (c ^ (r&7)) of row r.
// K B-frags: ldmatrix.x4 (rows = n, cols = k); V B-frags: ldmatrix.x4.trans.
// ---------------------------------------------------------------------------
#define FA_SMEM 65536

__global__ __launch_bounds__(256, 1)
void flash_attn_f16_kernel(const __half* __restrict__ Q, const __half* __restrict__ K,
                           const __half* __restrict__ V, float* __restrict__ AO)
{
    extern __shared__ __align__(16) __half smh[];
    const uint32_t sm0 = (uint32_t)__cvta_generic_to_shared(smh);

    const int tid  = threadIdx.x;
    const int w    = tid >> 5;
    const int lane = tid & 31;
    const int gid  = lane >> 2;
    const int tig  = lane & 3;
    const int bh   = blockIdx.y;
    const int q0   = blockIdx.x * 128;
    const float qscale = 0.125f * 1.44269504088896340736f;  // Hd^-0.5 * log2e

    const __half* Qb = Q + (size_t)bh * SEQ * HEAD_DIM;
    const __half* Kb = K + (size_t)bh * SEQ * HEAD_DIM;
    const __half* Vb = V + (size_t)bh * SEQ * HEAD_DIM;

    // ---- Q A-fragments in registers (half gmem -> scale -> half) ----
    unsigned qf[4][4];
    {
        const __half* q0p = Qb + (size_t)(q0 + w * 16 + gid) * HEAD_DIM;
        const __half* q1p = q0p + 8 * HEAD_DIM;
#pragma unroll
        for (int kkb = 0; kkb < 4; kkb++) {
            const int c = kkb * 16 + 2 * tig;
#pragma unroll
            for (int j = 0; j < 4; j++) {
                const __half* p = (j & 1) ? q1p : q0p;
                const int col  = c + (j >> 1) * 8;
                unsigned raw = *(const unsigned*)(p + col);
                float2 f = __half22float2(*reinterpret_cast<__half2*>(&raw));
                qf[kkb][j] = h2u(__floats2half2_rn(f.x * qscale, f.y * qscale));
            }
        }
    }

    // lane constants for ldmatrix addressing
    const int rl   = lane & 7;
    const int mK   = lane >> 3;             // matrix id 0..3
    const int K_cp = mK & 1;                // k-chunk parity (mat 1,3)
    const int kRow = (((lane >> 4) & 1) * 8 + rl) * 128;   // n-row bytes
    const int vKv  = (mK & 1) * 8 + rl;     // kv row within k16 block
    const int V_cp = mK >> 1;               // hd-chunk parity (mat 2,3)

    float m0v = -1e30f, m1v = -1e30f, l0 = 0.f, l1 = 0.f;
    float oacc[8][4];
#pragma unroll
    for (int nt = 0; nt < 8; nt++)
#pragma unroll
        for (int r = 0; r < 4; r++) oacc[nt][r] = 0.f;

    // ---- staging: 8 cp.async of 16B per thread per tile ----
    auto stage = [&](int buf, int kv0) {
        const uint32_t bb = sm0 + buf * 32768;
#pragma unroll
        for (int it = 0; it < 4; it++) {
            const int g   = tid + it * 256;      // chunk id 0..1023
            const int r   = g >> 3;
            const int c16 = g & 7;
            const uint32_t off = (uint32_t)(r * 128 + ((c16 ^ (r & 7)) * 16));
            const size_t gsrc = (size_t)(kv0 + r) * HEAD_DIM + c16 * 8;
            cp16(bb + off,         Kb + gsrc);
            cp16(bb + 16384 + off, Vb + gsrc);
        }
        asm volatile("cp.async.commit_group;");
    };

    stage(0, 0);

    for (int i = 0; i < 16; i++) {
        if (i > 0) __syncthreads();          // buffer (i+1)&1 free (tile i-1 done)
        if (i + 1 < 16) {
            stage((i + 1) & 1, (i + 1) * 128);
            asm volatile("cp.async.wait_group 1;");
        } else {
            asm volatile("cp.async.wait_group 0;");
        }
        __syncthreads();                     // tile i visible to all warps

        const uint32_t kb = sm0 + (i & 1) * 32768;
        const uint32_t vb = kb + 16384;

        // ---- S = Q K^T : 4 k16-blocks x 8 ldmatrix.x4 (2 n-tiles each) ----
        float sacc[16][4];
#pragma unroll
        for (int nt = 0; nt < 16; nt++)
#pragma unroll
            for (int r = 0; r < 4; r++) sacc[nt][r] = 0.f;

#pragma unroll
        for (int kkb = 0; kkb < 4; kkb++) {
            const uint32_t base = kb + kRow + (uint32_t)((((2 * kkb + K_cp) ^ rl)) * 16);
#pragma unroll
            for (int nt2 = 0; nt2 < 8; nt2++) {
                unsigned bfr[4];
                ldsm_x4(bfr, base + nt2 * 2048);
                mma_f16(sacc[2 * nt2],     qf[kkb], bfr);
                mma_f16(sacc[2 * nt2 + 1], qf[kkb], bfr + 2);
            }
        }

        // ---- online softmax in log2 domain (fp32) ----
        float rm0 = -1e30f, rm1 = -1e30f;
#pragma unroll
        for (int nt = 0; nt < 16; nt++) {
            rm0 = fmaxf(rm0, fmaxf(sacc[nt][0], sacc[nt][1]));
            rm1 = fmaxf(rm1, fmaxf(sacc[nt][2], sacc[nt][3]));
        }
        rm0 = fmaxf(rm0, __shfl_xor_sync(0xffffffffu, rm0, 1));
        rm0 = fmaxf(rm0, __shfl_xor_sync(0xffffffffu, rm0, 2));
        rm1 = fmaxf(rm1, __shfl_xor_sync(0xffffffffu, rm1, 1));
        rm1 = fmaxf(rm1, __shfl_xor_sync(0xffffffffu, rm1, 2));

        const float mn0 = fmaxf(m0v, rm0);
        const float mn1 = fmaxf(m1v, rm1);
        const float al0 = exp2f(m0v - mn0);
        const float al1 = exp2f(m1v - mn1);
        m0v = mn0; m1v = mn1;

        float rs0 = 0.f, rs1 = 0.f;
#pragma unroll
        for (int nt = 0; nt < 16; nt++) {
            sacc[nt][0] = exp2f(sacc[nt][0] - mn0);
            sacc[nt][1] = exp2f(sacc[nt][1] - mn0);
            sacc[nt][2] = exp2f(sacc[nt][2] - mn1);
            sacc[nt][3] = exp2f(sacc[nt][3] - mn1);
            rs0 += sacc[nt][0] + sacc[nt][1];
            rs1 += sacc[nt][2] + sacc[nt][3];
        }
        rs0 += __shfl_xor_sync(0xffffffffu, rs0, 1);
        rs0 += __shfl_xor_sync(0xffffffffu, rs0, 2);
        rs1 += __shfl_xor_sync(0xffffffffu, rs1, 1);
        rs1 += __shfl_xor_sync(0xffffffffu, rs1, 2);
        l0 = l0 * al0 + rs0;
        l1 = l1 * al1 + rs1;

#pragma unroll
        for (int nt = 0; nt < 8; nt++) {
            oacc[nt][0] *= al0; oacc[nt][1] *= al0;
            oacc[nt][2] *= al1; oacc[nt][3] *= al1;
        }

        // ---- O += P V : P from registers; V via ldmatrix.trans ----
#pragma unroll
        for (int kkb = 0; kkb < 8; kkb++) {
            unsigned ap[4];
            ap[0] = h2u(__floats2half2_rn(sacc[2*kkb][0],   sacc[2*kkb][1]));
            ap[1] = h2u(__floats2half2_rn(sacc[2*kkb][2],   sacc[2*kkb][3]));
            ap[2] = h2u(__floats2half2_rn(sacc[2*kkb+1][0], sacc[2*kkb+1][1]));
            ap[3] = h2u(__floats2half2_rn(sacc[2*kkb+1][2], sacc[2*kkb+1][3]));
            const uint32_t vrow = vb + (uint32_t)(vKv * 128 + kkb * 2048);
#pragma unroll
            for (int h2 = 0; h2 < 4; h2++) {
                unsigned bfr[4];
                ldsm_x4_t(bfr, vrow + (uint32_t)((((2 * h2 + V_cp) ^ rl)) * 16));
                mma_f16(oacc[2 * h2],     ap, bfr);
                mma_f16(oacc[2 * h2 + 1], ap, bfr + 2);
            }
        }
    }

    // Epilogue: normalize, write fp32 [B,S,D]
    const int r0l = w * 16 + gid;
    const int b = bh >> 4;
    const int h = bh & 15;
    const float inv0 = 1.0f / l0;
    const float inv1 = 1.0f / l1;
#pragma unroll
    for (int nt = 0; nt < 8; nt++) {
        const int col = h * HEAD_DIM + nt * 8 + 2 * tig;
        float2 v0 = make_float2(oacc[nt][0] * inv0, oacc[nt][1] * inv0);
        float2 v1 = make_float2(oacc[nt][2] * inv1, oacc[nt][3] * inv1);
        *(float2*)(AO + (size_t)(b * SEQ + q0 + r0l)     * D_MODEL + col) = v0;
        *(float2*)(AO + (size_t)(b * SEQ + q0 + r0l + 8) * D_MODEL + col) = v1;
    }
}

// ---------------------------------------------------------------------------
extern "C" void kernel_launch(void* const* d_in, const int* in_sizes, int n_in,
                              void* d_out, int out_size)
{
    const float* x  = (const float*)d_in[0];
    const float* wq = (const float*)d_in[1];
    const float* bq = (const float*)d_in[2];
    const float* wk = (const float*)d_in[3];
    const float* bk = (const float*)d_in[4];
    const float* wv = (const float*)d_in[5];
    const float* bv = (const float*)d_in[6];
    const float* wo = (const float*)d_in[7];
    const float* bo = (const float*)d_in[8];

    __half *Qp, *Kp, *Vp;
    float  *AOp;
    cudaGetSymbolAddress((void**)&Qp,  g_Q);
    cudaGetSymbolAddress((void**)&Kp,  g_K);
    cudaGetSymbolAddress((void**)&Vp,  g_V);
    cudaGetSymbolAddress((void**)&AOp, g_AO);

    const dim3 pg(D_MODEL / 128, MTOT / 128);   // (8, 64)

    gemm_f16_kernel<true><<<pg, 256>>>(x, wq, bq, Qp);
    gemm_f16_kernel<true><<<pg, 256>>>(x, wk, bk, Kp);
    gemm_f16_kernel<true><<<pg, 256>>>(x, wv, bv, Vp);

    cudaFuncSetAttribute(flash_attn_f16_kernel,
                         cudaFuncAttributeMaxDynamicSharedMemorySize, FA_SMEM);
    flash_attn_f16_kernel<<<dim3(SEQ / 128, BATCH * NUM_HEADS), 256, FA_SMEM>>>(Qp, Kp, Vp, AOp);

    gemm_f16_kernel<false><<<pg, 256>>>(AOp, wo, bo, d_out);
}

// round 15
// speedup vs baseline: 4.1766x; 1.4547x over previous
#include <cuda_runtime.h>
#include <cuda_fp16.h>
#include <cstdint>

#define D_MODEL   1024
#define NUM_HEADS 16
#define HEAD_DIM  64
#define BATCH     4
#define SEQ       2048
#define MTOT      (BATCH * SEQ)

// Scratch (allocation-free: __device__ globals), all fp16 now.
__device__ __half g_X [MTOT * D_MODEL];
__device__ __half g_Wq[D_MODEL * D_MODEL];
__device__ __half g_Wk[D_MODEL * D_MODEL];
__device__ __half g_Wv[D_MODEL * D_MODEL];
__device__ __half g_Wo[D_MODEL * D_MODEL];
__device__ __half g_Q [MTOT * D_MODEL];
__device__ __half g_K [MTOT * D_MODEL];
__device__ __half g_V [MTOT * D_MODEL];
__device__ __half g_AO[MTOT * D_MODEL];

// ---------------------------------------------------------------------------
// helpers
// ---------------------------------------------------------------------------
__device__ __forceinline__ void mma_f16(float c[4], const unsigned a[4],
                                        const unsigned b[2]) {
    asm volatile(
        "mma.sync.aligned.m16n8k16.row.col.f32.f16.f16.f32 "
        "{%0,%1,%2,%3}, {%4,%5,%6,%7}, {%8,%9}, {%0,%1,%2,%3};"
        : "+f"(c[0]), "+f"(c[1]), "+f"(c[2]), "+f"(c[3])
        : "r"(a[0]), "r"(a[1]), "r"(a[2]), "r"(a[3]), "r"(b[0]), "r"(b[1]));
}

__device__ __forceinline__ unsigned h2u(__half2 h) {
    return *reinterpret_cast<unsigned*>(&h);
}

__device__ __forceinline__ void ldsm_x4(unsigned r[4], uint32_t a) {
    asm volatile("ldmatrix.sync.aligned.m8n8.x4.shared.b16 {%0,%1,%2,%3}, [%4];"
        : "=r"(r[0]), "=r"(r[1]), "=r"(r[2]), "=r"(r[3]) : "r"(a));
}
__device__ __forceinline__ void ldsm_x4_t(unsigned r[4], uint32_t a) {
    asm volatile("ldmatrix.sync.aligned.m8n8.x4.trans.shared.b16 {%0,%1,%2,%3}, [%4];"
        : "=r"(r[0]), "=r"(r[1]), "=r"(r[2]), "=r"(r[3]) : "r"(a));
}
__device__ __forceinline__ void cp16(uint32_t dst, const void* src) {
    asm volatile("cp.async.cg.shared.global [%0], [%1], 16;" :: "r"(dst), "l"(src));
}

// ---------------------------------------------------------------------------
// fp32 -> fp16 convert, 8 elems/thread (2x LDG.128 -> 1x STG.128)
// ---------------------------------------------------------------------------
__global__ __launch_bounds__(256)
void cvt_f32_f16_kernel(const float* __restrict__ in, __half* __restrict__ out,
                        int n8)
{
    const int i = blockIdx.x * 256 + threadIdx.x;
    if (i >= n8) return;
    const float4 a = ((const float4*)in)[i * 2];
    const float4 b = ((const float4*)in)[i * 2 + 1];
    uint4 u;
    u.x = h2u(__floats2half2_rn(a.x, a.y));
    u.y = h2u(__floats2half2_rn(a.z, a.w));
    u.z = h2u(__floats2half2_rn(b.x, b.y));
    u.w = h2u(__floats2half2_rn(b.z, b.w));
    ((uint4*)out)[i] = u;
}

// ---------------------------------------------------------------------------
// fp16 GEMM v2 (NT): C[M,N] = A[M,K] @ W[N,K]^T + bias[N]
// A, W fp16 row-major (K-major). cp.async double-buffered tiles (BK=64),
// chunk-XOR swizzle (row r, 16B chunk c at c^(r&7)), ldmatrix.x4 fragments.
// Block 128x128, 8 warps (2m x 4n), warp 64x32. 64 KB dynamic smem.
// ---------------------------------------------------------------------------
template <bool SCATTER>
__global__ __launch_bounds__(256)
void gemm_f16_kernel(const __half* __restrict__ A, const __half* __restrict__ W,
                     const float* __restrict__ bias, void* __restrict__ Cv)
{
    extern __shared__ __align__(16) __half gsm[];
    const uint32_t sm0 = (uint32_t)__cvta_generic_to_shared(gsm);
    // buffer b: A tile at b*32768, W tile at b*32768 + 16384

    const int K = D_MODEL;
    const int tid    = threadIdx.x;
    const int wid    = tid >> 5;
    const int lane   = tid & 31;
    const int gid    = lane >> 2;
    const int tig    = lane & 3;
    const int warp_m = wid >> 2;
    const int warp_n = wid & 3;
    const int m0     = blockIdx.y * 128;
    const int n0     = blockIdx.x * 128;

    // ldmatrix lane constants
    const int rl   = lane & 7;
    const int mK   = lane >> 3;
    const int aRow = (mK & 1) * 8 + rl;            // A frag row-in-16
    const int aCp  = mK >> 1;                      // A k-chunk parity
    const int bRow = ((lane >> 4) & 1) * 8 + rl;   // B frag row-in-16
    const int bCp  = mK & 1;                       // B k-chunk parity

    float acc[4][4][4];
#pragma unroll
    for (int i = 0; i < 4; i++)
#pragma unroll
        for (int j = 0; j < 4; j++)
#pragma unroll
            for (int r = 0; r < 4; r++) acc[i][j][r] = 0.f;

    // staging: A/W tile = 128 rows x 8 chunks of 16B; 4+4 cp16 per thread
    const int sg_r = (tid * 4 + 0) >> 3;   // rows: thread covers 4 chunks
    // simpler: g = tid + it*256 over 1024 chunks
    auto stage = [&](int buf, int k0) {
        const uint32_t ab = sm0 + (uint32_t)buf * 32768u;
        const uint32_t wb = ab + 16384u;
#pragma unroll
        for (int it = 0; it < 4; it++) {
            const int g   = tid + it * 256;     // 0..1023
            const int r   = g >> 3;
            const int c16 = g & 7;
            const uint32_t off = (uint32_t)(r * 128 + ((c16 ^ (r & 7)) * 16));
            cp16(ab + off, A + (size_t)(m0 + r) * K + k0 + c16 * 8);
            cp16(wb + off, W + (size_t)(n0 + r) * K + k0 + c16 * 8);
        }
        asm volatile("cp.async.commit_group;");
    };

    stage(0, 0);

    const int NT = K / 64;   // 16
    for (int i = 0; i < NT; i++) {
        if (i > 0) __syncthreads();
        if (i + 1 < NT) {
            stage((i + 1) & 1, (i + 1) * 64);
            asm volatile("cp.async.wait_group 1;");
        } else {
            asm volatile("cp.async.wait_group 0;");
        }
        __syncthreads();

        const uint32_t ab = sm0 + (uint32_t)(i & 1) * 32768u;
        const uint32_t wb = ab + 16384u;

#pragma unroll
        for (int kkb = 0; kkb < 4; kkb++) {
            unsigned af[4][4];
#pragma unroll
            for (int mt = 0; mt < 4; mt++) {
                const int row = warp_m * 64 + mt * 16 + aRow;
                const int ch  = (2 * kkb + aCp) ^ rl;
                ldsm_x4(af[mt], ab + (uint32_t)(row * 128 + ch * 16));
            }
            unsigned bf[2][4];
#pragma unroll
            for (int nt2 = 0; nt2 < 2; nt2++) {
                const int row = warp_n * 32 + nt2 * 16 + bRow;
                const int ch  = (2 * kkb + bCp) ^ rl;
                ldsm_x4(bf[nt2], wb + (uint32_t)(row * 128 + ch * 16));
            }
#pragma unroll
            for (int mt = 0; mt < 4; mt++)
#pragma unroll
                for (int nt2 = 0; nt2 < 2; nt2++) {
                    mma_f16(acc[mt][2 * nt2],     af[mt], bf[nt2]);
                    mma_f16(acc[mt][2 * nt2 + 1], af[mt], bf[nt2] + 2);
                }
        }
    }

    // Epilogue (validated fragment->C mapping)
#pragma unroll
    for (int nt = 0; nt < 4; nt++) {
        const int n  = n0 + warp_n * 32 + nt * 8 + tig * 2;
        const float b0 = bias[n], b1 = bias[n + 1];
#pragma unroll
        for (int mt = 0; mt < 4; mt++) {
            const int m = m0 + warp_m * 64 + mt * 16 + gid;
            if (SCATTER) {
                __half* Ch = (__half*)Cv;
                const int h  = n >> 6;
                const int hd = n & 63;
                const int bb = m >> 11;
                const int s  = m & (SEQ - 1);
                unsigned u0 = h2u(__floats2half2_rn(acc[mt][nt][0] + b0,
                                                    acc[mt][nt][1] + b1));
                unsigned u1 = h2u(__floats2half2_rn(acc[mt][nt][2] + b0,
                                                    acc[mt][nt][3] + b1));
                *(unsigned*)(Ch + ((size_t)((bb * NUM_HEADS + h) * SEQ + s))     * HEAD_DIM + hd) = u0;
                *(unsigned*)(Ch + ((size_t)((bb * NUM_HEADS + h) * SEQ + s + 8)) * HEAD_DIM + hd) = u1;
            } else {
                float* Cf = (float*)Cv;
                float2 v0 = make_float2(acc[mt][nt][0] + b0, acc[mt][nt][1] + b1);
                float2 v1 = make_float2(acc[mt][nt][2] + b0, acc[mt][nt][3] + b1);
                *(float2*)(Cf + (size_t)m * D_MODEL + n)       = v0;
                *(float2*)(Cf + (size_t)(m + 8) * D_MODEL + n) = v1;
            }
        }
    }
}

// ---------------------------------------------------------------------------
// Flash attention v8 (R14, 222 us): cp.async double-buffered K/V, ldmatrix,
// register-resident P, exp2 softmax. Only change: AO written as fp16.
// ---------------------------------------------------------------------------
#define FA_SMEM 65536

__global__ __launch_bounds__(256, 1)
void flash_attn_f16_kernel(const __half* __restrict__ Q, const __half* __restrict__ K,
                           const __half* __restrict__ V, __half* __restrict__ AO)
{
    extern __shared__ __align__(16) __half smh[];
    const uint32_t sm0 = (uint32_t)__cvta_generic_to_shared(smh);

    const int tid  = threadIdx.x;
    const int w    = tid >> 5;
    const int lane = tid & 31;
    const int gid  = lane >> 2;
    const int tig  = lane & 3;
    const int bh   = blockIdx.y;
    const int q0   = blockIdx.x * 128;
    const float qscale = 0.125f * 1.44269504088896340736f;  // Hd^-0.5 * log2e

    const __half* Qb = Q + (size_t)bh * SEQ * HEAD_DIM;
    const __half* Kb = K + (size_t)bh * SEQ * HEAD_DIM;
    const __half* Vb = V + (size_t)bh * SEQ * HEAD_DIM;

    // ---- Q A-fragments in registers (half gmem -> scale -> half) ----
    unsigned qf[4][4];
    {
        const __half* q0p = Qb + (size_t)(q0 + w * 16 + gid) * HEAD_DIM;
        const __half* q1p = q0p + 8 * HEAD_DIM;
#pragma unroll
        for (int kkb = 0; kkb < 4; kkb++) {
            const int c = kkb * 16 + 2 * tig;
#pragma unroll
            for (int j = 0; j < 4; j++) {
                const __half* p = (j & 1) ? q1p : q0p;
                const int col  = c + (j >> 1) * 8;
                unsigned raw = *(const unsigned*)(p + col);
                float2 f = __half22float2(*reinterpret_cast<__half2*>(&raw));
                qf[kkb][j] = h2u(__floats2half2_rn(f.x * qscale, f.y * qscale));
            }
        }
    }

    // lane constants for ldmatrix addressing
    const int rl   = lane & 7;
    const int mK   = lane >> 3;
    const int K_cp = mK & 1;
    const int kRow = (((lane >> 4) & 1) * 8 + rl) * 128;
    const int vKv  = (mK & 1) * 8 + rl;
    const int V_cp = mK >> 1;

    float m0v = -1e30f, m1v = -1e30f, l0 = 0.f, l1 = 0.f;
    float oacc[8][4];
#pragma unroll
    for (int nt = 0; nt < 8; nt++)
#pragma unroll
        for (int r = 0; r < 4; r++) oacc[nt][r] = 0.f;

    auto stage = [&](int buf, int kv0) {
        const uint32_t bb = sm0 + buf * 32768;
#pragma unroll
        for (int it = 0; it < 4; it++) {
            const int g   = tid + it * 256;
            const int r   = g >> 3;
            const int c16 = g & 7;
            const uint32_t off = (uint32_t)(r * 128 + ((c16 ^ (r & 7)) * 16));
            const size_t gsrc = (size_t)(kv0 + r) * HEAD_DIM + c16 * 8;
            cp16(bb + off,         Kb + gsrc);
            cp16(bb + 16384 + off, Vb + gsrc);
        }
        asm volatile("cp.async.commit_group;");
    };

    stage(0, 0);

    for (int i = 0; i < 16; i++) {
        if (i > 0) __syncthreads();
        if (i + 1 < 16) {
            stage((i + 1) & 1, (i + 1) * 128);
            asm volatile("cp.async.wait_group 1;");
        } else {
            asm volatile("cp.async.wait_group 0;");
        }
        __syncthreads();

        const uint32_t kb = sm0 + (i & 1) * 32768;
        const uint32_t vb = kb + 16384;

        // ---- S = Q K^T ----
        float sacc[16][4];
#pragma unroll
        for (int nt = 0; nt < 16; nt++)
#pragma unroll
            for (int r = 0; r < 4; r++) sacc[nt][r] = 0.f;

#pragma unroll
        for (int kkb = 0; kkb < 4; kkb++) {
            const uint32_t base = kb + kRow + (uint32_t)((((2 * kkb + K_cp) ^ rl)) * 16);
#pragma unroll
            for (int nt2 = 0; nt2 < 8; nt2++) {
                unsigned bfr[4];
                ldsm_x4(bfr, base + nt2 * 2048);
                mma_f16(sacc[2 * nt2],     qf[kkb], bfr);
                mma_f16(sacc[2 * nt2 + 1], qf[kkb], bfr + 2);
            }
        }

        // ---- online softmax in log2 domain (fp32) ----
        float rm0 = -1e30f, rm1 = -1e30f;
#pragma unroll
        for (int nt = 0; nt < 16; nt++) {
            rm0 = fmaxf(rm0, fmaxf(sacc[nt][0], sacc[nt][1]));
            rm1 = fmaxf(rm1, fmaxf(sacc[nt][2], sacc[nt][3]));
        }
        rm0 = fmaxf(rm0, __shfl_xor_sync(0xffffffffu, rm0, 1));
        rm0 = fmaxf(rm0, __shfl_xor_sync(0xffffffffu, rm0, 2));
        rm1 = fmaxf(rm1, __shfl_xor_sync(0xffffffffu, rm1, 1));
        rm1 = fmaxf(rm1, __shfl_xor_sync(0xffffffffu, rm1, 2));

        const float mn0 = fmaxf(m0v, rm0);
        const float mn1 = fmaxf(m1v, rm1);
        const float al0 = exp2f(m0v - mn0);
        const float al1 = exp2f(m1v - mn1);
        m0v = mn0; m1v = mn1;

        float rs0 = 0.f, rs1 = 0.f;
#pragma unroll
        for (int nt = 0; nt < 16; nt++) {
            sacc[nt][0] = exp2f(sacc[nt][0] - mn0);
            sacc[nt][1] = exp2f(sacc[nt][1] - mn0);
            sacc[nt][2] = exp2f(sacc[nt][2] - mn1);
            sacc[nt][3] = exp2f(sacc[nt][3] - mn1);
            rs0 += sacc[nt][0] + sacc[nt][1];
            rs1 += sacc[nt][2] + sacc[nt][3];
        }
        rs0 += __shfl_xor_sync(0xffffffffu, rs0, 1);
        rs0 += __shfl_xor_sync(0xffffffffu, rs0, 2);
        rs1 += __shfl_xor_sync(0xffffffffu, rs1, 1);
        rs1 += __shfl_xor_sync(0xffffffffu, rs1, 2);
        l0 = l0 * al0 + rs0;
        l1 = l1 * al1 + rs1;

#pragma unroll
        for (int nt = 0; nt < 8; nt++) {
            oacc[nt][0] *= al0; oacc[nt][1] *= al0;
            oacc[nt][2] *= al1; oacc[nt][3] *= al1;
        }

        // ---- O += P V ----
#pragma unroll
        for (int kkb = 0; kkb < 8; kkb++) {
            unsigned ap[4];
            ap[0] = h2u(__floats2half2_rn(sacc[2*kkb][0],   sacc[2*kkb][1]));
            ap[1] = h2u(__floats2half2_rn(sacc[2*kkb][2],   sacc[2*kkb][3]));
            ap[2] = h2u(__floats2half2_rn(sacc[2*kkb+1][0], sacc[2*kkb+1][1]));
            ap[3] = h2u(__floats2half2_rn(sacc[2*kkb+1][2], sacc[2*kkb+1][3]));
            const uint32_t vrow = vb + (uint32_t)(vKv * 128 + kkb * 2048);
#pragma unroll
            for (int h2 = 0; h2 < 4; h2++) {
                unsigned bfr[4];
                ldsm_x4_t(bfr, vrow + (uint32_t)((((2 * h2 + V_cp) ^ rl)) * 16));
                mma_f16(oacc[2 * h2],     ap, bfr);
                mma_f16(oacc[2 * h2 + 1], ap, bfr + 2);
            }
        }
    }

    // Epilogue: normalize, write fp16 [B,S,D]
    const int r0l = w * 16 + gid;
    const int b = bh >> 4;
    const int h = bh & 15;
    const float inv0 = 1.0f / l0;
    const float inv1 = 1.0f / l1;
#pragma unroll
    for (int nt = 0; nt < 8; nt++) {
        const int col = h * HEAD_DIM + nt * 8 + 2 * tig;
        unsigned u0 = h2u(__floats2half2_rn(oacc[nt][0] * inv0, oacc[nt][1] * inv0));
        unsigned u1 = h2u(__floats2half2_rn(oacc[nt][2] * inv1, oacc[nt][3] * inv1));
        *(unsigned*)(AO + (size_t)(b * SEQ + q0 + r0l)     * D_MODEL + col) = u0;
        *(unsigned*)(AO + (size_t)(b * SEQ + q0 + r0l + 8) * D_MODEL + col) = u1;
    }
}

// ---------------------------------------------------------------------------
extern "C" void kernel_launch(void* const* d_in, const int* in_sizes, int n_in,
                              void* d_out, int out_size)
{
    const float* x  = (const float*)d_in[0];
    const float* wq = (const float*)d_in[1];
    const float* bq = (const float*)d_in[2];
    const float* wk = (const float*)d_in[3];
    const float* bk = (const float*)d_in[4];
    const float* wv = (const float*)d_in[5];
    const float* bv = (const float*)d_in[6];
    const float* wo = (const float*)d_in[7];
    const float* bo = (const float*)d_in[8];

    __half *Xp, *Wqp, *Wkp, *Wvp, *Wop, *Qp, *Kp, *Vp, *AOp;
    cudaGetSymbolAddress((void**)&Xp,  g_X);
    cudaGetSymbolAddress((void**)&Wqp, g_Wq);
    cudaGetSymbolAddress((void**)&Wkp, g_Wk);
    cudaGetSymbolAddress((void**)&Wvp, g_Wv);
    cudaGetSymbolAddress((void**)&Wop, g_Wo);
    cudaGetSymbolAddress((void**)&Qp,  g_Q);
    cudaGetSymbolAddress((void**)&Kp,  g_K);
    cudaGetSymbolAddress((void**)&Vp,  g_V);
    cudaGetSymbolAddress((void**)&AOp, g_AO);

    // fp32 -> fp16 converts
    const int xW8 = MTOT * D_MODEL / 8;         // 1,048,576
    const int wW8 = D_MODEL * D_MODEL / 8;      // 131,072
    cvt_f32_f16_kernel<<<(xW8 + 255) / 256, 256>>>(x,  Xp,  xW8);
    cvt_f32_f16_kernel<<<(wW8 + 255) / 256, 256>>>(wq, Wqp, wW8);
    cvt_f32_f16_kernel<<<(wW8 + 255) / 256, 256>>>(wk, Wkp, wW8);
    cvt_f32_f16_kernel<<<(wW8 + 255) / 256, 256>>>(wv, Wvp, wW8);
    cvt_f32_f16_kernel<<<(wW8 + 255) / 256, 256>>>(wo, Wop, wW8);

    const dim3 pg(D_MODEL / 128, MTOT / 128);   // (8, 64)
    const int GEMM_SMEM = 65536;
    cudaFuncSetAttribute(gemm_f16_kernel<true>,
                         cudaFuncAttributeMaxDynamicSharedMemorySize, GEMM_SMEM);
    cudaFuncSetAttribute(gemm_f16_kernel<false>,
                         cudaFuncAttributeMaxDynamicSharedMemorySize, GEMM_SMEM);

    gemm_f16_kernel<true><<<pg, 256, GEMM_SMEM>>>(Xp, Wqp, bq, Qp);
    gemm_f16_kernel<true><<<pg, 256, GEMM_SMEM>>>(Xp, Wkp, bk, Kp);
    gemm_f16_kernel<true><<<pg, 256, GEMM_SMEM>>>(Xp, Wvp, bv, Vp);

    cudaFuncSetAttribute(flash_attn_f16_kernel,
                         cudaFuncAttributeMaxDynamicSharedMemorySize, FA_SMEM);
    flash_attn_f16_kernel<<<dim3(SEQ / 128, BATCH * NUM_HEADS), 256, FA_SMEM>>>(Qp, Kp, Vp, AOp);

    gemm_f16_kernel<false><<<pg, 256, GEMM_SMEM>>>(AOp, Wop, bo, d_out);
}